// round 2
// baseline (speedup 1.0000x reference)
#include <cuda_runtime.h>
#include <cuda_bf16.h>
#include <math.h>

// ---------------------------------------------------------------------------
// Problem constants
// ---------------------------------------------------------------------------
#define BB   16
#define SS   1024
#define EE   1024
#define HH   16
#define HD   64
#define FFN  4096
#define MM   (BB * SS)          // 16384 rows

// ---------------------------------------------------------------------------
// Scratch buffers (device globals: allocation-free, graph-capture safe)
// ---------------------------------------------------------------------------
__device__ float g_h   [(size_t)MM * EE];       // LN outputs (reused)
__device__ float g_qkv [(size_t)MM * 3 * EE];   // fused QKV
__device__ float g_attn[(size_t)MM * EE];       // attention output
__device__ float g_x2  [(size_t)MM * EE];       // residual after attention
__device__ float g_ffn [(size_t)MM * FFN];      // FFN hidden

// ---------------------------------------------------------------------------
// LayerNorm: one block per row, E=1024, 256 threads x float4
// ---------------------------------------------------------------------------
__global__ __launch_bounds__(256)
void ln_kernel(const float* __restrict__ x, const float* __restrict__ w,
               const float* __restrict__ b, float* __restrict__ y)
{
    const long row = blockIdx.x;
    const float4* xr = (const float4*)(x + (row << 10));
    float4 xv = xr[threadIdx.x];

    float s  = xv.x + xv.y + xv.z + xv.w;
    float sq = xv.x * xv.x + xv.y * xv.y + xv.z * xv.z + xv.w * xv.w;
    #pragma unroll
    for (int o = 16; o; o >>= 1) {
        s  += __shfl_xor_sync(0xffffffffu, s,  o);
        sq += __shfl_xor_sync(0xffffffffu, sq, o);
    }
    __shared__ float ss[8], ssq[8];
    __shared__ float mu_s, rstd_s;
    const int warp = threadIdx.x >> 5, lane = threadIdx.x & 31;
    if (lane == 0) { ss[warp] = s; ssq[warp] = sq; }
    __syncthreads();
    if (threadIdx.x == 0) {
        float S = 0.f, SQ = 0.f;
        #pragma unroll
        for (int i = 0; i < 8; i++) { S += ss[i]; SQ += ssq[i]; }
        const float mu  = S * (1.0f / 1024.0f);
        const float var = SQ * (1.0f / 1024.0f) - mu * mu;
        mu_s   = mu;
        rstd_s = rsqrtf(var + 1e-6f);
    }
    __syncthreads();
    const float mu = mu_s, rstd = rstd_s;

    const float4 wv = ((const float4*)w)[threadIdx.x];
    const float4 bv = ((const float4*)b)[threadIdx.x];
    float4 o;
    o.x = (xv.x - mu) * rstd * wv.x + bv.x;
    o.y = (xv.y - mu) * rstd * wv.y + bv.y;
    o.z = (xv.z - mu) * rstd * wv.z + bv.z;
    o.w = (xv.w - mu) * rstd * wv.w + bv.w;
    ((float4*)(y + (row << 10)))[threadIdx.x] = o;
}

// ---------------------------------------------------------------------------
// GEMM: C[M,N] = A[M,K] @ W[N,K]^T + bias, optional epilogue
//   128x128 block tile, BK=16, 256 threads, 8x8 micro-tile per thread,
//   transposed smem tiles ([k][m]) for conflict-free float4 LDS,
//   register prefetch of the next K-tile to overlap LDG with FFMA.
// ---------------------------------------------------------------------------
#define EPI_NONE 0
#define EPI_GELU 1
#define EPI_RES  2

template<int EPI>
__global__ __launch_bounds__(256)
void gemm_kernel(const float* __restrict__ A, const float* __restrict__ W,
                 const float* __restrict__ bias, const float* __restrict__ Res,
                 float* __restrict__ C, int M, int N, int K)
{
    __shared__ float As[16][132];
    __shared__ float Bs[16][132];

    const int tid  = threadIdx.x;
    const int bm   = blockIdx.y * 128;
    const int bn   = blockIdx.x * 128;
    const int lrow = tid >> 2;            // 0..63
    const int lk   = (tid & 3) << 2;      // 0,4,8,12
    const int tx   = tid & 15;
    const int ty   = tid >> 4;

    const float* Ap = A + (long)(bm + lrow) * K + lk;
    const float* Wp = W + (long)(bn + lrow) * K + lk;

    float acc[8][8];
    #pragma unroll
    for (int i = 0; i < 8; i++)
        #pragma unroll
        for (int j = 0; j < 8; j++) acc[i][j] = 0.f;

    float4 a0 = *(const float4*)Ap;
    float4 a1 = *(const float4*)(Ap + (long)64 * K);
    float4 b0 = *(const float4*)Wp;
    float4 b1 = *(const float4*)(Wp + (long)64 * K);

    const int ntiles = K >> 4;
    for (int t = 0; t < ntiles; ++t) {
        As[lk + 0][lrow]      = a0.x; As[lk + 1][lrow]      = a0.y;
        As[lk + 2][lrow]      = a0.z; As[lk + 3][lrow]      = a0.w;
        As[lk + 0][lrow + 64] = a1.x; As[lk + 1][lrow + 64] = a1.y;
        As[lk + 2][lrow + 64] = a1.z; As[lk + 3][lrow + 64] = a1.w;
        Bs[lk + 0][lrow]      = b0.x; Bs[lk + 1][lrow]      = b0.y;
        Bs[lk + 2][lrow]      = b0.z; Bs[lk + 3][lrow]      = b0.w;
        Bs[lk + 0][lrow + 64] = b1.x; Bs[lk + 1][lrow + 64] = b1.y;
        Bs[lk + 2][lrow + 64] = b1.z; Bs[lk + 3][lrow + 64] = b1.w;
        __syncthreads();

        if (t + 1 < ntiles) {           // prefetch next tile into registers
            const float* Ap2 = Ap + (t + 1) * 16;
            const float* Wp2 = Wp + (t + 1) * 16;
            a0 = *(const float4*)Ap2;
            a1 = *(const float4*)(Ap2 + (long)64 * K);
            b0 = *(const float4*)Wp2;
            b1 = *(const float4*)(Wp2 + (long)64 * K);
        }

        #pragma unroll
        for (int k = 0; k < 16; k++) {
            const float4 af0 = *(const float4*)&As[k][ty * 8];
            const float4 af1 = *(const float4*)&As[k][ty * 8 + 4];
            const float4 bf0 = *(const float4*)&Bs[k][tx * 8];
            const float4 bf1 = *(const float4*)&Bs[k][tx * 8 + 4];
            const float ar[8] = {af0.x, af0.y, af0.z, af0.w, af1.x, af1.y, af1.z, af1.w};
            const float br[8] = {bf0.x, bf0.y, bf0.z, bf0.w, bf1.x, bf1.y, bf1.z, bf1.w};
            #pragma unroll
            for (int i = 0; i < 8; i++)
                #pragma unroll
                for (int j = 0; j < 8; j++)
                    acc[i][j] = fmaf(ar[i], br[j], acc[i][j]);
        }
        __syncthreads();
    }

    // epilogue
    #pragma unroll
    for (int i = 0; i < 8; i++) {
        const long row = bm + ty * 8 + i;
        float* Crow = C + row * (long)N + bn + tx * 8;
        const float* Rrow = (EPI == EPI_RES) ? (Res + row * (long)N + bn + tx * 8)
                                             : (const float*)nullptr;
        #pragma unroll
        for (int jv = 0; jv < 2; jv++) {
            float4 out;
            float* o = (float*)&out;
            #pragma unroll
            for (int j = 0; j < 4; j++) {
                const int col = tx * 8 + jv * 4 + j;
                float v = acc[i][jv * 4 + j] + bias[bn + col];
                if (EPI == EPI_GELU)
                    v = 0.5f * v * (1.0f + erff(v * 0.7071067811865475f));
                if (EPI == EPI_RES)
                    v += Rrow[jv * 4 + j];
                o[j] = v;
            }
            *(float4*)(Crow + jv * 4) = out;
        }
    }
}

// ---------------------------------------------------------------------------
// Flash attention: grid (S/64, B*H), 256 threads.
//   64 query rows per block, key tiles of 32, online softmax.
//   Thread t owns q-row r = t/4; score cols j ≡ t%4 (mod 4);
//   output cols d in [ (t%4)*16, (t%4)*16+16 ).
// ---------------------------------------------------------------------------
__global__ __launch_bounds__(256)
void attn_kernel(const float* __restrict__ qkv, float* __restrict__ out)
{
    __shared__ float Qs[64][68];
    __shared__ float Ks[32][68];
    __shared__ float Vs[32][68];
    __shared__ float Ps[64][36];

    const int tid = threadIdx.x;
    const int bh  = blockIdx.y;               // b*H + h
    const int b   = bh >> 4;
    const int h   = bh & 15;
    const int q0  = blockIdx.x * 64;
    const long base = (long)b * SS * 3072 + (long)h * HD;

    // load Q tile (64 x 64)
    {
        const int row = tid >> 2, dblk = (tid & 3) * 16;
        const float* src = qkv + base + (long)(q0 + row) * 3072 + dblk;
        *(float4*)&Qs[row][dblk]      = *(const float4*)(src);
        *(float4*)&Qs[row][dblk + 4]  = *(const float4*)(src + 4);
        *(float4*)&Qs[row][dblk + 8]  = *(const float4*)(src + 8);
        *(float4*)&Qs[row][dblk + 12] = *(const float4*)(src + 12);
    }

    const int r  = tid >> 2;
    const int jl = tid & 3;
    float m = -1e30f, l = 0.f;
    float O[16];
    #pragma unroll
    for (int i = 0; i < 16; i++) O[i] = 0.f;

    for (int kt = 0; kt < 32; ++kt) {
        const int key0 = kt * 32;
        {   // load K,V tiles (32 x 64 each)
            const int row = tid >> 3, dblk = (tid & 7) * 8;
            const float* ks = qkv + base + 1024 + (long)(key0 + row) * 3072 + dblk;
            const float* vs = qkv + base + 2048 + (long)(key0 + row) * 3072 + dblk;
            *(float4*)&Ks[row][dblk]     = *(const float4*)ks;
            *(float4*)&Ks[row][dblk + 4] = *(const float4*)(ks + 4);
            *(float4*)&Vs[row][dblk]     = *(const float4*)vs;
            *(float4*)&Vs[row][dblk + 4] = *(const float4*)(vs + 4);
        }
        __syncthreads();

        // scores: thread computes s[jj] for j = jl + 4*jj
        float s[8];
        #pragma unroll
        for (int jj = 0; jj < 8; jj++) s[jj] = 0.f;
        #pragma unroll
        for (int d4 = 0; d4 < 16; ++d4) {
            const float4 q = *(const float4*)&Qs[r][d4 * 4];
            #pragma unroll
            for (int jj = 0; jj < 8; jj++) {
                const float4 kk = *(const float4*)&Ks[jl + jj * 4][d4 * 4];
                s[jj] += q.x * kk.x + q.y * kk.y + q.z * kk.z + q.w * kk.w;
            }
        }

        float mt = -1e30f;
        #pragma unroll
        for (int jj = 0; jj < 8; jj++) { s[jj] *= 0.125f; mt = fmaxf(mt, s[jj]); }
        mt = fmaxf(mt, __shfl_xor_sync(0xffffffffu, mt, 1));
        mt = fmaxf(mt, __shfl_xor_sync(0xffffffffu, mt, 2));
        const float m_new = fmaxf(m, mt);
        const float corr  = __expf(m - m_new);

        float psum = 0.f;
        #pragma unroll
        for (int jj = 0; jj < 8; jj++) {
            const float p = __expf(s[jj] - m_new);
            Ps[r][jl + jj * 4] = p;
            psum += p;
        }
        psum += __shfl_xor_sync(0xffffffffu, psum, 1);
        psum += __shfl_xor_sync(0xffffffffu, psum, 2);
        l = l * corr + psum;
        m = m_new;
        #pragma unroll
        for (int i = 0; i < 16; i++) O[i] *= corr;
        __syncthreads();                 // Ps visible to row partners

        // O += P @ V : thread owns d = jl*16 .. jl*16+15
        #pragma unroll
        for (int j = 0; j < 32; j++) {
            const float p = Ps[r][j];
            const float4 v0 = *(const float4*)&Vs[j][jl * 16];
            const float4 v1 = *(const float4*)&Vs[j][jl * 16 + 4];
            const float4 v2 = *(const float4*)&Vs[j][jl * 16 + 8];
            const float4 v3 = *(const float4*)&Vs[j][jl * 16 + 12];
            O[0]  = fmaf(p, v0.x, O[0]);  O[1]  = fmaf(p, v0.y, O[1]);
            O[2]  = fmaf(p, v0.z, O[2]);  O[3]  = fmaf(p, v0.w, O[3]);
            O[4]  = fmaf(p, v1.x, O[4]);  O[5]  = fmaf(p, v1.y, O[5]);
            O[6]  = fmaf(p, v1.z, O[6]);  O[7]  = fmaf(p, v1.w, O[7]);
            O[8]  = fmaf(p, v2.x, O[8]);  O[9]  = fmaf(p, v2.y, O[9]);
            O[10] = fmaf(p, v2.z, O[10]); O[11] = fmaf(p, v2.w, O[11]);
            O[12] = fmaf(p, v3.x, O[12]); O[13] = fmaf(p, v3.y, O[13]);
            O[14] = fmaf(p, v3.z, O[14]); O[15] = fmaf(p, v3.w, O[15]);
        }
        __syncthreads();                 // protect K/V/Ps before next tile
    }

    const float inv_l = 1.0f / l;
    float* dst = out + (long)(b * SS + q0 + r) * EE + h * HD + jl * 16;
    #pragma unroll
    for (int v4 = 0; v4 < 4; v4++) {
        float4 o;
        o.x = O[v4 * 4 + 0] * inv_l;
        o.y = O[v4 * 4 + 1] * inv_l;
        o.z = O[v4 * 4 + 2] * inv_l;
        o.w = O[v4 * 4 + 3] * inv_l;
        *(float4*)(dst + v4 * 4) = o;
    }
}

// ---------------------------------------------------------------------------
// Launch sequence
// ---------------------------------------------------------------------------
extern "C" void kernel_launch(void* const* d_in, const int* in_sizes, int n_in,
                              void* d_out, int out_size)
{
    const float* x         = (const float*)d_in[0];
    const float* ln1_w     = (const float*)d_in[1];
    const float* ln1_b     = (const float*)d_in[2];
    const float* ln2_w     = (const float*)d_in[3];
    const float* ln2_b     = (const float*)d_in[4];
    const float* in_proj_w = (const float*)d_in[5];
    const float* in_proj_b = (const float*)d_in[6];
    const float* out_w     = (const float*)d_in[7];
    const float* out_b     = (const float*)d_in[8];
    const float* w1        = (const float*)d_in[9];
    const float* b1        = (const float*)d_in[10];
    const float* w2        = (const float*)d_in[11];
    const float* b2        = (const float*)d_in[12];
    float* outp            = (float*)d_out;

    float *h, *qkv, *attn, *x2, *ffn;
    cudaGetSymbolAddress((void**)&h,    g_h);
    cudaGetSymbolAddress((void**)&qkv,  g_qkv);
    cudaGetSymbolAddress((void**)&attn, g_attn);
    cudaGetSymbolAddress((void**)&x2,   g_x2);
    cudaGetSymbolAddress((void**)&ffn,  g_ffn);

    // 1. h = LN1(x)
    ln_kernel<<<MM, 256>>>(x, ln1_w, ln1_b, h);
    // 2. qkv = h @ in_proj_w^T + in_proj_b            [16384, 3072]
    gemm_kernel<EPI_NONE><<<dim3(3 * EE / 128, MM / 128), 256>>>(
        h, in_proj_w, in_proj_b, nullptr, qkv, MM, 3 * EE, EE);
    // 3. attn = softmax(QK^T/sqrt(hd)) V              [16384, 1024]
    attn_kernel<<<dim3(SS / 64, BB * HH), 256>>>(qkv, attn);
    // 4. x2 = x + attn @ out_w^T + out_b
    gemm_kernel<EPI_RES><<<dim3(EE / 128, MM / 128), 256>>>(
        attn, out_w, out_b, x, x2, MM, EE, EE);
    // 5. h = LN2(x2)
    ln_kernel<<<MM, 256>>>(x2, ln2_w, ln2_b, h);
    // 6. ffn = gelu(h @ w1^T + b1)                    [16384, 4096]
    gemm_kernel<EPI_GELU><<<dim3(FFN / 128, MM / 128), 256>>>(
        h, w1, b1, nullptr, ffn, MM, FFN, EE);
    // 7. out = x2 + ffn @ w2^T + b2
    gemm_kernel<EPI_RES><<<dim3(EE / 128, MM / 128), 256>>>(
        ffn, w2, b2, x2, outp, MM, EE, FFN);
}

// round 5
// speedup vs baseline: 1.5296x; 1.5296x over previous
#include <cuda_runtime.h>
#include <cuda_bf16.h>
#include <math.h>
#include <stdint.h>

// ---------------------------------------------------------------------------
// Problem constants
// ---------------------------------------------------------------------------
#define BB   16
#define SS   1024
#define EE   1024
#define HH   16
#define HD   64
#define FFN  4096
#define MM   (BB * SS)          // 16384 rows

// ---------------------------------------------------------------------------
// Scratch buffers (device globals: allocation-free, graph-capture safe)
// ---------------------------------------------------------------------------
__device__ float g_h   [(size_t)MM * EE];
__device__ float g_qkv [(size_t)MM * 3 * EE];
__device__ float g_attn[(size_t)MM * EE];
__device__ float g_x2  [(size_t)MM * EE];
__device__ float g_ffn [(size_t)MM * FFN];

// ---------------------------------------------------------------------------
// PTX helpers (sm_100 plain target: cp.async + mma.sync only)
// ---------------------------------------------------------------------------
__device__ __forceinline__ uint32_t smem_u32(const void* p) {
    uint32_t a;
    asm("{ .reg .u64 t; cvta.to.shared.u64 t, %1; cvt.u32.u64 %0, t; }"
        : "=r"(a) : "l"(p));
    return a;
}

__device__ __forceinline__ void cp_async16(uint32_t dst, const void* src) {
    asm volatile("cp.async.cg.shared.global [%0], [%1], 16;"
                 :: "r"(dst), "l"(src) : "memory");
}
#define CP_COMMIT() asm volatile("cp.async.commit_group;" ::: "memory")
#define CP_WAIT2()  asm volatile("cp.async.wait_group 2;" ::: "memory")

#define MMA_TF32(c, a, b) \
    asm volatile("mma.sync.aligned.m16n8k8.row.col.f32.tf32.tf32.f32 " \
        "{%0,%1,%2,%3}, {%4,%5,%6,%7}, {%8,%9}, {%0,%1,%2,%3};" \
        : "+f"((c)[0]), "+f"((c)[1]), "+f"((c)[2]), "+f"((c)[3]) \
        : "r"((a)[0]), "r"((a)[1]), "r"((a)[2]), "r"((a)[3]), \
          "r"((b)[0]), "r"((b)[1]))

// ---------------------------------------------------------------------------
// tf32 mma.sync GEMM: C[M,N] = A[M,K] @ W[N,K]^T + bias (+gelu / +residual)
//   128x128 CTA tile, BK=32, 8 warps (2x4), warp tile 64x32,
//   3-stage cp.async pipeline, padded smem (stride 36 -> conflict-free).
// ---------------------------------------------------------------------------
#define EPI_NONE 0
#define EPI_GELU 1
#define EPI_RES  2

#define GBK       32
#define GSTAGES   3
#define LSTRIDE   36                          // floats per smem row (144B)
#define STAGE_FLT (2 * 128 * LSTRIDE)         // A block then B block
#define DSMEM_SZ  (GSTAGES * STAGE_FLT * 4)   // 110592 bytes

template<int EPI>
__global__ __launch_bounds__(256)
void gemm_mma(const float* __restrict__ A, const float* __restrict__ W,
              const float* __restrict__ bias, const float* __restrict__ Res,
              float* __restrict__ C, int N, int K)
{
    extern __shared__ float sm[];
    const uint32_t smA = smem_u32(sm);

    const int tid  = threadIdx.x;
    const int bm   = blockIdx.y * 128;
    const int bn   = blockIdx.x * 128;
    const int warp = tid >> 5, lane = tid & 31;
    const int wm   = (warp >> 2) * 64;        // 0,64
    const int wn   = (warp & 3) * 32;         // 0,32,64,96
    const int qr   = lane >> 2;               // 0..7
    const int qc   = lane & 3;                // 0..3

    float acc[4][4][4];
    #pragma unroll
    for (int i = 0; i < 4; i++)
        #pragma unroll
        for (int j = 0; j < 4; j++)
            #pragma unroll
            for (int k = 0; k < 4; k++) acc[i][j][k] = 0.f;

    // cp.async mapping: thread -> row tid>>1, col block (tid&1)*16, 4 x 16B
    const int  lrow = tid >> 1;
    const int  lcol = (tid & 1) * 16;
    const float* Ap = A + (long)(bm + lrow) * K + lcol;
    const float* Wp = W + (long)(bn + lrow) * K + lcol;
    const uint32_t dstA = smA + (lrow * LSTRIDE + lcol) * 4;
    const uint32_t dstB = smA + ((128 + lrow) * LSTRIDE + lcol) * 4;

    const int T = K / GBK;

    // prologue: stages 0,1
    #pragma unroll
    for (int u = 0; u < 2; ++u) {
        const uint32_t sb = u * (STAGE_FLT * 4);
        #pragma unroll
        for (int j = 0; j < 4; j++) {
            cp_async16(dstA + sb + j * 16, Ap + (long)u * GBK + j * 4);
            cp_async16(dstB + sb + j * 16, Wp + (long)u * GBK + j * 4);
        }
        CP_COMMIT();
    }

    for (int t = 0; t < T; ++t) {
        if (t + 2 < T) {
            const int u = t + 2;
            const uint32_t sb = (u % GSTAGES) * (STAGE_FLT * 4);
            #pragma unroll
            for (int j = 0; j < 4; j++) {
                cp_async16(dstA + sb + j * 16, Ap + (long)u * GBK + j * 4);
                cp_async16(dstB + sb + j * 16, Wp + (long)u * GBK + j * 4);
            }
        }
        CP_COMMIT();
        CP_WAIT2();
        __syncthreads();

        const float* As = sm + (t % GSTAGES) * STAGE_FLT;
        const float* Bs = As + 128 * LSTRIDE;

        #pragma unroll
        for (int ks = 0; ks < 4; ++ks) {
            uint32_t a[4][4], b[4][2];
            #pragma unroll
            for (int mt = 0; mt < 4; ++mt) {
                const float* p = As + (wm + mt * 16 + qr) * LSTRIDE + ks * 8 + qc;
                a[mt][0] = __float_as_uint(p[0]);
                a[mt][1] = __float_as_uint(p[8 * LSTRIDE]);
                a[mt][2] = __float_as_uint(p[4]);
                a[mt][3] = __float_as_uint(p[8 * LSTRIDE + 4]);
            }
            #pragma unroll
            for (int nt = 0; nt < 4; ++nt) {
                const float* p = Bs + (wn + nt * 8 + qr) * LSTRIDE + ks * 8 + qc;
                b[nt][0] = __float_as_uint(p[0]);
                b[nt][1] = __float_as_uint(p[4]);
            }
            #pragma unroll
            for (int mt = 0; mt < 4; ++mt)
                #pragma unroll
                for (int nt = 0; nt < 4; ++nt)
                    MMA_TF32(acc[mt][nt], a[mt], b[nt]);
        }
        __syncthreads();
    }

    // epilogue: c0/c1 at (row=qr, cols 2qc,2qc+1), c2/c3 at row qr+8
    #pragma unroll
    for (int mt = 0; mt < 4; ++mt) {
        #pragma unroll
        for (int r2 = 0; r2 < 2; ++r2) {
            const long row = bm + wm + mt * 16 + qr + r2 * 8;
            float* Crow = C + row * (long)N + bn;
            const float* Rrow = (EPI == EPI_RES) ? (Res + row * (long)N + bn)
                                                 : (const float*)nullptr;
            #pragma unroll
            for (int nt = 0; nt < 4; ++nt) {
                const int col = wn + nt * 8 + qc * 2;
                float2 v;
                v.x = acc[mt][nt][r2 * 2 + 0];
                v.y = acc[mt][nt][r2 * 2 + 1];
                const float2 bv = *(const float2*)(bias + bn + col);
                v.x += bv.x; v.y += bv.y;
                if (EPI == EPI_GELU) {
                    v.x = 0.5f * v.x * (1.0f + erff(v.x * 0.7071067811865475f));
                    v.y = 0.5f * v.y * (1.0f + erff(v.y * 0.7071067811865475f));
                }
                if (EPI == EPI_RES) {
                    const float2 rv = *(const float2*)(Rrow + col);
                    v.x += rv.x; v.y += rv.y;
                }
                *(float2*)(Crow + col) = v;
            }
        }
    }
}

// ---------------------------------------------------------------------------
// LayerNorm (unchanged)
// ---------------------------------------------------------------------------
__global__ __launch_bounds__(256)
void ln_kernel(const float* __restrict__ x, const float* __restrict__ w,
               const float* __restrict__ b, float* __restrict__ y)
{
    const long row = blockIdx.x;
    const float4* xr = (const float4*)(x + (row << 10));
    float4 xv = xr[threadIdx.x];

    float s  = xv.x + xv.y + xv.z + xv.w;
    float sq = xv.x * xv.x + xv.y * xv.y + xv.z * xv.z + xv.w * xv.w;
    #pragma unroll
    for (int o = 16; o; o >>= 1) {
        s  += __shfl_xor_sync(0xffffffffu, s,  o);
        sq += __shfl_xor_sync(0xffffffffu, sq, o);
    }
    __shared__ float ss[8], ssq[8];
    __shared__ float mu_s, rstd_s;
    const int warp = threadIdx.x >> 5, lane = threadIdx.x & 31;
    if (lane == 0) { ss[warp] = s; ssq[warp] = sq; }
    __syncthreads();
    if (threadIdx.x == 0) {
        float S = 0.f, SQ = 0.f;
        #pragma unroll
        for (int i = 0; i < 8; i++) { S += ss[i]; SQ += ssq[i]; }
        const float mu  = S * (1.0f / 1024.0f);
        const float var = SQ * (1.0f / 1024.0f) - mu * mu;
        mu_s   = mu;
        rstd_s = rsqrtf(var + 1e-6f);
    }
    __syncthreads();
    const float mu = mu_s, rstd = rstd_s;

    const float4 wv = ((const float4*)w)[threadIdx.x];
    const float4 bv = ((const float4*)b)[threadIdx.x];
    float4 o;
    o.x = (xv.x - mu) * rstd * wv.x + bv.x;
    o.y = (xv.y - mu) * rstd * wv.y + bv.y;
    o.z = (xv.z - mu) * rstd * wv.z + bv.z;
    o.w = (xv.w - mu) * rstd * wv.w + bv.w;
    ((float4*)(y + (row << 10)))[threadIdx.x] = o;
}

// ---------------------------------------------------------------------------
// Flash attention (unchanged this round)
// ---------------------------------------------------------------------------
__global__ __launch_bounds__(256)
void attn_kernel(const float* __restrict__ qkv, float* __restrict__ out)
{
    __shared__ float Qs[64][68];
    __shared__ float Ks[32][68];
    __shared__ float Vs[32][68];
    __shared__ float Ps[64][36];

    const int tid = threadIdx.x;
    const int bh  = blockIdx.y;
    const int b   = bh >> 4;
    const int h   = bh & 15;
    const int q0  = blockIdx.x * 64;
    const long base = (long)b * SS * 3072 + (long)h * HD;

    {
        const int row = tid >> 2, dblk = (tid & 3) * 16;
        const float* src = qkv + base + (long)(q0 + row) * 3072 + dblk;
        *(float4*)&Qs[row][dblk]      = *(const float4*)(src);
        *(float4*)&Qs[row][dblk + 4]  = *(const float4*)(src + 4);
        *(float4*)&Qs[row][dblk + 8]  = *(const float4*)(src + 8);
        *(float4*)&Qs[row][dblk + 12] = *(const float4*)(src + 12);
    }

    const int r  = tid >> 2;
    const int jl = tid & 3;
    float m = -1e30f, l = 0.f;
    float O[16];
    #pragma unroll
    for (int i = 0; i < 16; i++) O[i] = 0.f;

    for (int kt = 0; kt < 32; ++kt) {
        const int key0 = kt * 32;
        {
            const int row = tid >> 3, dblk = (tid & 7) * 8;
            const float* ks = qkv + base + 1024 + (long)(key0 + row) * 3072 + dblk;
            const float* vs = qkv + base + 2048 + (long)(key0 + row) * 3072 + dblk;
            *(float4*)&Ks[row][dblk]     = *(const float4*)ks;
            *(float4*)&Ks[row][dblk + 4] = *(const float4*)(ks + 4);
            *(float4*)&Vs[row][dblk]     = *(const float4*)vs;
            *(float4*)&Vs[row][dblk + 4] = *(const float4*)(vs + 4);
        }
        __syncthreads();

        float s[8];
        #pragma unroll
        for (int jj = 0; jj < 8; jj++) s[jj] = 0.f;
        #pragma unroll
        for (int d4 = 0; d4 < 16; ++d4) {
            const float4 q = *(const float4*)&Qs[r][d4 * 4];
            #pragma unroll
            for (int jj = 0; jj < 8; jj++) {
                const float4 kk = *(const float4*)&Ks[jl + jj * 4][d4 * 4];
                s[jj] += q.x * kk.x + q.y * kk.y + q.z * kk.z + q.w * kk.w;
            }
        }

        float mt = -1e30f;
        #pragma unroll
        for (int jj = 0; jj < 8; jj++) { s[jj] *= 0.125f; mt = fmaxf(mt, s[jj]); }
        mt = fmaxf(mt, __shfl_xor_sync(0xffffffffu, mt, 1));
        mt = fmaxf(mt, __shfl_xor_sync(0xffffffffu, mt, 2));
        const float m_new = fmaxf(m, mt);
        const float corr  = __expf(m - m_new);

        float psum = 0.f;
        #pragma unroll
        for (int jj = 0; jj < 8; jj++) {
            const float p = __expf(s[jj] - m_new);
            Ps[r][jl + jj * 4] = p;
            psum += p;
        }
        psum += __shfl_xor_sync(0xffffffffu, psum, 1);
        psum += __shfl_xor_sync(0xffffffffu, psum, 2);
        l = l * corr + psum;
        m = m_new;
        #pragma unroll
        for (int i = 0; i < 16; i++) O[i] *= corr;
        __syncthreads();

        #pragma unroll
        for (int j = 0; j < 32; j++) {
            const float p = Ps[r][j];
            const float4 v0 = *(const float4*)&Vs[j][jl * 16];
            const float4 v1 = *(const float4*)&Vs[j][jl * 16 + 4];
            const float4 v2 = *(const float4*)&Vs[j][jl * 16 + 8];
            const float4 v3 = *(const float4*)&Vs[j][jl * 16 + 12];
            O[0]  = fmaf(p, v0.x, O[0]);  O[1]  = fmaf(p, v0.y, O[1]);
            O[2]  = fmaf(p, v0.z, O[2]);  O[3]  = fmaf(p, v0.w, O[3]);
            O[4]  = fmaf(p, v1.x, O[4]);  O[5]  = fmaf(p, v1.y, O[5]);
            O[6]  = fmaf(p, v1.z, O[6]);  O[7]  = fmaf(p, v1.w, O[7]);
            O[8]  = fmaf(p, v2.x, O[8]);  O[9]  = fmaf(p, v2.y, O[9]);
            O[10] = fmaf(p, v2.z, O[10]); O[11] = fmaf(p, v2.w, O[11]);
            O[12] = fmaf(p, v3.x, O[12]); O[13] = fmaf(p, v3.y, O[13]);
            O[14] = fmaf(p, v3.z, O[14]); O[15] = fmaf(p, v3.w, O[15]);
        }
        __syncthreads();
    }

    const float inv_l = 1.0f / l;
    float* dst = out + (long)(b * SS + q0 + r) * EE + h * HD + jl * 16;
    #pragma unroll
    for (int v4 = 0; v4 < 4; v4++) {
        float4 o;
        o.x = O[v4 * 4 + 0] * inv_l;
        o.y = O[v4 * 4 + 1] * inv_l;
        o.z = O[v4 * 4 + 2] * inv_l;
        o.w = O[v4 * 4 + 3] * inv_l;
        *(float4*)(dst + v4 * 4) = o;
    }
}

// ---------------------------------------------------------------------------
// Launch sequence
// ---------------------------------------------------------------------------
extern "C" void kernel_launch(void* const* d_in, const int* in_sizes, int n_in,
                              void* d_out, int out_size)
{
    const float* x         = (const float*)d_in[0];
    const float* ln1_w     = (const float*)d_in[1];
    const float* ln1_b     = (const float*)d_in[2];
    const float* ln2_w     = (const float*)d_in[3];
    const float* ln2_b     = (const float*)d_in[4];
    const float* in_proj_w = (const float*)d_in[5];
    const float* in_proj_b = (const float*)d_in[6];
    const float* out_w     = (const float*)d_in[7];
    const float* out_b     = (const float*)d_in[8];
    const float* w1        = (const float*)d_in[9];
    const float* b1        = (const float*)d_in[10];
    const float* w2        = (const float*)d_in[11];
    const float* b2        = (const float*)d_in[12];
    float* outp            = (float*)d_out;

    float *h, *qkv, *attn, *x2, *ffn;
    cudaGetSymbolAddress((void**)&h,    g_h);
    cudaGetSymbolAddress((void**)&qkv,  g_qkv);
    cudaGetSymbolAddress((void**)&attn, g_attn);
    cudaGetSymbolAddress((void**)&x2,   g_x2);
    cudaGetSymbolAddress((void**)&ffn,  g_ffn);

    cudaFuncSetAttribute(gemm_mma<EPI_NONE>, cudaFuncAttributeMaxDynamicSharedMemorySize, DSMEM_SZ);
    cudaFuncSetAttribute(gemm_mma<EPI_GELU>, cudaFuncAttributeMaxDynamicSharedMemorySize, DSMEM_SZ);
    cudaFuncSetAttribute(gemm_mma<EPI_RES>,  cudaFuncAttributeMaxDynamicSharedMemorySize, DSMEM_SZ);

    // 1. h = LN1(x)
    ln_kernel<<<MM, 256>>>(x, ln1_w, ln1_b, h);
    // 2. qkv = h @ in_proj_w^T + b                    [16384, 3072]
    gemm_mma<EPI_NONE><<<dim3(3 * EE / 128, MM / 128), 256, DSMEM_SZ>>>(
        h, in_proj_w, in_proj_b, nullptr, qkv, 3 * EE, EE);
    // 3. attention
    attn_kernel<<<dim3(SS / 64, BB * HH), 256>>>(qkv, attn);
    // 4. x2 = x + attn @ out_w^T + out_b
    gemm_mma<EPI_RES><<<dim3(EE / 128, MM / 128), 256, DSMEM_SZ>>>(
        attn, out_w, out_b, x, x2, EE, EE);
    // 5. h = LN2(x2)
    ln_kernel<<<MM, 256>>>(x2, ln2_w, ln2_b, h);
    // 6. ffn = gelu(h @ w1^T + b1)                    [16384, 4096]
    gemm_mma<EPI_GELU><<<dim3(FFN / 128, MM / 128), 256, DSMEM_SZ>>>(
        h, w1, b1, nullptr, ffn, FFN, EE);
    // 7. out = x2 + ffn @ w2^T + b2
    gemm_mma<EPI_RES><<<dim3(EE / 128, MM / 128), 256, DSMEM_SZ>>>(
        ffn, w2, b2, x2, outp, EE, FFN);
}

// round 8
// speedup vs baseline: 3.7206x; 2.4325x over previous
#include <cuda_runtime.h>
#include <cuda_bf16.h>
#include <math.h>
#include <stdint.h>

// ---------------------------------------------------------------------------
// Problem constants
// ---------------------------------------------------------------------------
#define BB   16
#define SS   1024
#define EE   1024
#define HH   16
#define HD   64
#define FFN  4096
#define MM   (BB * SS)          // 16384 rows

// ---------------------------------------------------------------------------
// Scratch buffers (device globals: allocation-free, graph-capture safe)
// ---------------------------------------------------------------------------
__device__ float g_h   [(size_t)MM * EE];
__device__ float g_qkv [(size_t)MM * 3 * EE];
__device__ float g_attn[(size_t)MM * EE];
__device__ float g_x2  [(size_t)MM * EE];
__device__ float g_ffn [(size_t)MM * FFN];

// ---------------------------------------------------------------------------
// PTX helpers (sm_100 plain target: cp.async + mma.sync only)
// ---------------------------------------------------------------------------
__device__ __forceinline__ uint32_t smem_u32(const void* p) {
    uint32_t a;
    asm("{ .reg .u64 t; cvta.to.shared.u64 t, %1; cvt.u32.u64 %0, t; }"
        : "=r"(a) : "l"(p));
    return a;
}

__device__ __forceinline__ void cp_async16(uint32_t dst, const void* src) {
    asm volatile("cp.async.cg.shared.global [%0], [%1], 16;"
                 :: "r"(dst), "l"(src) : "memory");
}
#define CP_COMMIT() asm volatile("cp.async.commit_group;" ::: "memory")
#define CP_WAIT(n)  asm volatile("cp.async.wait_group %0;" :: "n"(n) : "memory")

// round-to-nearest fp32 -> tf32 (unbiased; halves error vs raw truncation)
__device__ __forceinline__ uint32_t f2tf(float x) {
    uint32_t r;
    asm("cvt.rna.tf32.f32 %0, %1;" : "=r"(r) : "f"(x));
    return r;
}

#define MMA_TF32(c, a, b) \
    asm volatile("mma.sync.aligned.m16n8k8.row.col.f32.tf32.tf32.f32 " \
        "{%0,%1,%2,%3}, {%4,%5,%6,%7}, {%8,%9}, {%0,%1,%2,%3};" \
        : "+f"((c)[0]), "+f"((c)[1]), "+f"((c)[2]), "+f"((c)[3]) \
        : "r"((a)[0]), "r"((a)[1]), "r"((a)[2]), "r"((a)[3]), \
          "r"((b)[0]), "r"((b)[1]))

// ---------------------------------------------------------------------------
// tf32 mma.sync GEMM: C[M,N] = A[M,K] @ W[N,K]^T + bias (+gelu / +residual)
//   128x128 CTA tile, BK=32, 8 warps (2x4), warp tile 64x32,
//   3-stage cp.async pipeline, XOR-swizzled smem (32KB/stage -> 2 CTA/SM).
// ---------------------------------------------------------------------------
#define EPI_NONE 0
#define EPI_GELU 1
#define EPI_RES  2

#define GBK       32
#define GSTAGES   3
#define STAGE_FLT (2 * 128 * 32)              // A block then B block (floats)
#define DSMEM_SZ  (GSTAGES * STAGE_FLT * 4)   // 98304 bytes

// logical (row r, float col w in 0..31) -> physical float index (XOR swizzle)
#define SWIDX(r, w) \
    (((r) << 5) + (((((w) >> 2) ^ ((r) & 7)) << 2) | ((w) & 3)))

template<int EPI>
__global__ __launch_bounds__(256, 2)
void gemm_mma(const float* __restrict__ A, const float* __restrict__ W,
              const float* __restrict__ bias, const float* __restrict__ Res,
              float* __restrict__ C, int N, int K)
{
    extern __shared__ float sm[];
    const uint32_t smA = smem_u32(sm);

    const int tid  = threadIdx.x;
    const int bm   = blockIdx.y * 128;
    const int bn   = blockIdx.x * 128;
    const int warp = tid >> 5, lane = tid & 31;
    const int wm   = (warp >> 2) * 64;        // 0,64
    const int wn   = (warp & 3) * 32;         // 0,32,64,96
    const int qr   = lane >> 2;               // 0..7
    const int qc   = lane & 3;                // 0..3

    float acc[4][4][4];
    #pragma unroll
    for (int i = 0; i < 4; i++)
        #pragma unroll
        for (int j = 0; j < 4; j++)
            #pragma unroll
            for (int k = 0; k < 4; k++) acc[i][j][k] = 0.f;

    // cp.async mapping: thread -> row tid>>1, chunk base (tid&1)*4, 4 x 16B
    const int  lrow = tid >> 1;
    const int  cb   = (tid & 1) * 4;
    const float* Ap = A + (long)(bm + lrow) * K;
    const float* Wp = W + (long)(bn + lrow) * K;
    const uint32_t dA = smA + lrow * 128;
    const uint32_t dB = smA + (128 + lrow) * 128;
    const int rx = lrow & 7;

    const int T = K / GBK;

    // prologue: stages 0,1
    #pragma unroll
    for (int u = 0; u < 2; ++u) {
        const uint32_t sb = u * (STAGE_FLT * 4);
        #pragma unroll
        for (int j = 0; j < 4; j++) {
            const int c = cb + j;
            const uint32_t so = ((c ^ rx) << 4);
            cp_async16(dA + sb + so, Ap + (long)u * GBK + c * 4);
            cp_async16(dB + sb + so, Wp + (long)u * GBK + c * 4);
        }
        CP_COMMIT();
    }

    for (int t = 0; t < T; ++t) {
        if (t + 2 < T) {
            const int u = t + 2;
            const uint32_t sb = (u % GSTAGES) * (STAGE_FLT * 4);
            #pragma unroll
            for (int j = 0; j < 4; j++) {
                const int c = cb + j;
                const uint32_t so = ((c ^ rx) << 4);
                cp_async16(dA + sb + so, Ap + (long)u * GBK + c * 4);
                cp_async16(dB + sb + so, Wp + (long)u * GBK + c * 4);
            }
        }
        CP_COMMIT();
        CP_WAIT(2);
        __syncthreads();

        const float* As = sm + (t % GSTAGES) * STAGE_FLT;
        const float* Bs = As + 128 * 32;

        #pragma unroll
        for (int ks = 0; ks < 4; ++ks) {
            uint32_t a[4][4], b[4][2];
            #pragma unroll
            for (int mt = 0; mt < 4; ++mt) {
                const int r0 = wm + mt * 16 + qr, r1 = r0 + 8;
                a[mt][0] = f2tf(As[SWIDX(r0, ks * 8 + qc)]);
                a[mt][1] = f2tf(As[SWIDX(r1, ks * 8 + qc)]);
                a[mt][2] = f2tf(As[SWIDX(r0, ks * 8 + qc + 4)]);
                a[mt][3] = f2tf(As[SWIDX(r1, ks * 8 + qc + 4)]);
            }
            #pragma unroll
            for (int nt = 0; nt < 4; ++nt) {
                const int r = wn + nt * 8 + qr;
                b[nt][0] = f2tf(Bs[SWIDX(r, ks * 8 + qc)]);
                b[nt][1] = f2tf(Bs[SWIDX(r, ks * 8 + qc + 4)]);
            }
            #pragma unroll
            for (int mt = 0; mt < 4; ++mt)
                #pragma unroll
                for (int nt = 0; nt < 4; ++nt)
                    MMA_TF32(acc[mt][nt], a[mt], b[nt]);
        }
        __syncthreads();
    }

    // epilogue
    #pragma unroll
    for (int mt = 0; mt < 4; ++mt) {
        #pragma unroll
        for (int r2 = 0; r2 < 2; ++r2) {
            const long row = bm + wm + mt * 16 + qr + r2 * 8;
            float* Crow = C + row * (long)N + bn;
            const float* Rrow = (EPI == EPI_RES) ? (Res + row * (long)N + bn)
                                                 : (const float*)nullptr;
            #pragma unroll
            for (int nt = 0; nt < 4; ++nt) {
                const int col = wn + nt * 8 + qc * 2;
                float2 v;
                v.x = acc[mt][nt][r2 * 2 + 0];
                v.y = acc[mt][nt][r2 * 2 + 1];
                const float2 bv = *(const float2*)(bias + bn + col);
                v.x += bv.x; v.y += bv.y;
                if (EPI == EPI_GELU) {
                    v.x = 0.5f * v.x * (1.0f + erff(v.x * 0.7071067811865475f));
                    v.y = 0.5f * v.y * (1.0f + erff(v.y * 0.7071067811865475f));
                }
                if (EPI == EPI_RES) {
                    const float2 rv = *(const float2*)(Rrow + col);
                    v.x += rv.x; v.y += rv.y;
                }
                *(float2*)(Crow + col) = v;
            }
        }
    }
}

// ---------------------------------------------------------------------------
// LayerNorm (unchanged)
// ---------------------------------------------------------------------------
__global__ __launch_bounds__(256)
void ln_kernel(const float* __restrict__ x, const float* __restrict__ w,
               const float* __restrict__ b, float* __restrict__ y)
{
    const long row = blockIdx.x;
    const float4* xr = (const float4*)(x + (row << 10));
    float4 xv = xr[threadIdx.x];

    float s  = xv.x + xv.y + xv.z + xv.w;
    float sq = xv.x * xv.x + xv.y * xv.y + xv.z * xv.z + xv.w * xv.w;
    #pragma unroll
    for (int o = 16; o; o >>= 1) {
        s  += __shfl_xor_sync(0xffffffffu, s,  o);
        sq += __shfl_xor_sync(0xffffffffu, sq, o);
    }
    __shared__ float ss[8], ssq[8];
    __shared__ float mu_s, rstd_s;
    const int warp = threadIdx.x >> 5, lane = threadIdx.x & 31;
    if (lane == 0) { ss[warp] = s; ssq[warp] = sq; }
    __syncthreads();
    if (threadIdx.x == 0) {
        float S = 0.f, SQ = 0.f;
        #pragma unroll
        for (int i = 0; i < 8; i++) { S += ss[i]; SQ += ssq[i]; }
        const float mu  = S * (1.0f / 1024.0f);
        const float var = SQ * (1.0f / 1024.0f) - mu * mu;
        mu_s   = mu;
        rstd_s = rsqrtf(var + 1e-6f);
    }
    __syncthreads();
    const float mu = mu_s, rstd = rstd_s;

    const float4 wv = ((const float4*)w)[threadIdx.x];
    const float4 bv = ((const float4*)b)[threadIdx.x];
    float4 o;
    o.x = (xv.x - mu) * rstd * wv.x + bv.x;
    o.y = (xv.y - mu) * rstd * wv.y + bv.y;
    o.z = (xv.z - mu) * rstd * wv.z + bv.z;
    o.w = (xv.w - mu) * rstd * wv.w + bv.w;
    ((float4*)(y + (row << 10)))[threadIdx.x] = o;
}

// ---------------------------------------------------------------------------
// Flash attention with tf32 mma.sync
//   64 q-rows/CTA, 4 warps (1 m16-tile each), 32-key tiles double-buffered.
//   Q*K^T: A=Q regs, B=K smem (K-major = col-major B, stride 68, bank-free).
//   Softmax in registers (warp-private rows, quad shuffles).
//   P via warp-local smem tile (stride 36); P*V with V gathered from
//   row-major smem (stride 72 -> bank-free fragment loads).
// ---------------------------------------------------------------------------
#define AQ_STR 68
#define AK_STR 68
#define AV_STR 72
#define AP_STR 36
#define AQ_FLT (64 * AQ_STR)              // 4352
#define AK_FLT (2 * 32 * AK_STR)          // 4352
#define AV_FLT (2 * 32 * AV_STR)          // 4608
#define AP_FLT (64 * AP_STR)              // 2304
#define ATTN_SMEM ((AQ_FLT + AK_FLT + AV_FLT + AP_FLT) * 4)  // 62464 B

__global__ __launch_bounds__(128)
void attn_mma(const float* __restrict__ qkv, float* __restrict__ out)
{
    extern __shared__ float asmem[];
    float* Qs = asmem;
    float* Ks = Qs + AQ_FLT;
    float* Vs = Ks + AK_FLT;
    float* Ps = Vs + AV_FLT;

    const int tid  = threadIdx.x;
    const int warp = tid >> 5, lane = tid & 31;
    const int qr   = lane >> 2, qc = lane & 3;
    const int b    = blockIdx.y >> 4, h = blockIdx.y & 15;
    const int q0   = blockIdx.x * 64;
    const int wm   = warp * 16;
    const long base = (long)b * SS * 3072 + h * 64;

    const uint32_t sQ = smem_u32(Qs), sK = smem_u32(Ks), sV = smem_u32(Vs);

    // Q tile (64 rows x 64 floats = 1024 16B-chunks): 8 per thread
    #pragma unroll
    for (int i = 0; i < 8; i++) {
        const int cc = tid + i * 128;
        const int row = cc >> 4, c = cc & 15;    // 16 chunks per row
        cp_async16(sQ + (row * AQ_STR + c * 4) * 4,
                   qkv + base + (long)(q0 + row) * 3072 + c * 4);
    }
    // K/V tile kt=0 (32 rows x 64 floats = 512 chunks each): 4 per thread each
    #pragma unroll
    for (int i = 0; i < 4; i++) {
        const int cc = tid + i * 128;
        const int row = cc >> 4, c = cc & 15;
        const long ko = base + 1024 + (long)row * 3072 + c * 4;
        cp_async16(sK + (row * AK_STR + c * 4) * 4, qkv + ko);
        cp_async16(sV + (row * AV_STR + c * 4) * 4, qkv + ko + 1024);
    }
    CP_COMMIT();
    CP_WAIT(0);
    __syncthreads();

    // Q fragments: scaled by 1/8 (exact), tf32-rounded, register-resident
    uint32_t qa[8][4];
    {
        const int r0 = wm + qr, r1 = r0 + 8;
        #pragma unroll
        for (int ks = 0; ks < 8; ks++) {
            qa[ks][0] = f2tf(Qs[r0 * AQ_STR + ks * 8 + qc] * 0.125f);
            qa[ks][1] = f2tf(Qs[r1 * AQ_STR + ks * 8 + qc] * 0.125f);
            qa[ks][2] = f2tf(Qs[r0 * AQ_STR + ks * 8 + qc + 4] * 0.125f);
            qa[ks][3] = f2tf(Qs[r1 * AQ_STR + ks * 8 + qc + 4] * 0.125f);
        }
    }

    float o[8][4];
    #pragma unroll
    for (int nt = 0; nt < 8; nt++)
        #pragma unroll
        for (int k = 0; k < 4; k++) o[nt][k] = 0.f;
    float mrow0 = -1e30f, mrow1 = -1e30f, l0 = 0.f, l1 = 0.f;

    for (int kt = 0; kt < 32; kt++) {
        const int cur = kt & 1;
        __syncthreads();                       // all warps done with buf cur^1
        if (kt + 1 < 32) {
            const int nxt = cur ^ 1;
            #pragma unroll
            for (int i = 0; i < 4; i++) {
                const int cc = tid + i * 128;
                const int row = cc >> 4, c = cc & 15;
                const long ko = base + 1024
                              + (long)((kt + 1) * 32 + row) * 3072 + c * 4;
                cp_async16(sK + ((nxt * 32 + row) * AK_STR + c * 4) * 4, qkv + ko);
                cp_async16(sV + ((nxt * 32 + row) * AV_STR + c * 4) * 4, qkv + ko + 1024);
            }
        }
        CP_COMMIT();
        CP_WAIT(1);
        __syncthreads();

        const float* Kc = Ks + cur * 32 * AK_STR;
        const float* Vc = Vs + cur * 32 * AV_STR;

        // S = (Q/8) K^T  (warp tile 16 x 32 keys)
        float s[4][4];
        #pragma unroll
        for (int nt = 0; nt < 4; nt++)
            #pragma unroll
            for (int k = 0; k < 4; k++) s[nt][k] = 0.f;
        #pragma unroll
        for (int ks = 0; ks < 8; ks++) {
            uint32_t bf[4][2];
            #pragma unroll
            for (int nt = 0; nt < 4; nt++) {
                const float* p = Kc + (nt * 8 + qr) * AK_STR + ks * 8 + qc;
                bf[nt][0] = f2tf(p[0]);
                bf[nt][1] = f2tf(p[4]);
            }
            #pragma unroll
            for (int nt = 0; nt < 4; nt++)
                MMA_TF32(s[nt], qa[ks], bf[nt]);
        }

        // online softmax (rows r0 = wm+qr, r1 = wm+qr+8; quad owns each row)
        float m0 = -1e30f, m1 = -1e30f;
        #pragma unroll
        for (int nt = 0; nt < 4; nt++) {
            m0 = fmaxf(m0, fmaxf(s[nt][0], s[nt][1]));
            m1 = fmaxf(m1, fmaxf(s[nt][2], s[nt][3]));
        }
        m0 = fmaxf(m0, __shfl_xor_sync(0xffffffffu, m0, 1));
        m0 = fmaxf(m0, __shfl_xor_sync(0xffffffffu, m0, 2));
        m1 = fmaxf(m1, __shfl_xor_sync(0xffffffffu, m1, 1));
        m1 = fmaxf(m1, __shfl_xor_sync(0xffffffffu, m1, 2));
        const float n0 = fmaxf(mrow0, m0), n1 = fmaxf(mrow1, m1);
        const float c0 = __expf(mrow0 - n0), c1 = __expf(mrow1 - n1);
        float ps0 = 0.f, ps1 = 0.f;
        float* P0 = Ps + (wm + qr) * AP_STR + 2 * qc;
        float* P1 = Ps + (wm + qr + 8) * AP_STR + 2 * qc;
        #pragma unroll
        for (int nt = 0; nt < 4; nt++) {
            const float p00 = __expf(s[nt][0] - n0);
            const float p01 = __expf(s[nt][1] - n0);
            const float p10 = __expf(s[nt][2] - n1);
            const float p11 = __expf(s[nt][3] - n1);
            ps0 += p00 + p01;
            ps1 += p10 + p11;
            P0[nt * 8 + 0] = __uint_as_float(f2tf(p00));
            P0[nt * 8 + 1] = __uint_as_float(f2tf(p01));
            P1[nt * 8 + 0] = __uint_as_float(f2tf(p10));
            P1[nt * 8 + 1] = __uint_as_float(f2tf(p11));
        }
        ps0 += __shfl_xor_sync(0xffffffffu, ps0, 1);
        ps0 += __shfl_xor_sync(0xffffffffu, ps0, 2);
        ps1 += __shfl_xor_sync(0xffffffffu, ps1, 1);
        ps1 += __shfl_xor_sync(0xffffffffu, ps1, 2);
        l0 = l0 * c0 + ps0;
        l1 = l1 * c1 + ps1;
        mrow0 = n0; mrow1 = n1;
        #pragma unroll
        for (int nt = 0; nt < 8; nt++) {
            o[nt][0] *= c0; o[nt][1] *= c0;
            o[nt][2] *= c1; o[nt][3] *= c1;
        }
        __syncwarp();                          // P visible within warp

        // O += P V  (k = 32 keys, n = 64 hd)
        #pragma unroll
        for (int ks2 = 0; ks2 < 4; ks2++) {
            uint32_t pa[4];
            pa[0] = __float_as_uint(Ps[(wm + qr) * AP_STR + ks2 * 8 + qc]);
            pa[1] = __float_as_uint(Ps[(wm + qr + 8) * AP_STR + ks2 * 8 + qc]);
            pa[2] = __float_as_uint(Ps[(wm + qr) * AP_STR + ks2 * 8 + qc + 4]);
            pa[3] = __float_as_uint(Ps[(wm + qr + 8) * AP_STR + ks2 * 8 + qc + 4]);
            #pragma unroll
            for (int nt = 0; nt < 8; nt++) {
                uint32_t bv[2];
                bv[0] = f2tf(Vc[(ks2 * 8 + qc) * AV_STR + nt * 8 + qr]);
                bv[1] = f2tf(Vc[(ks2 * 8 + qc + 4) * AV_STR + nt * 8 + qr]);
                MMA_TF32(o[nt], pa, bv);
            }
        }
        __syncwarp();                          // P reads done before next write
    }

    const float i0 = 1.0f / l0, i1 = 1.0f / l1;
    const long r0g = (long)(b * SS + q0 + wm + qr);
    float* d0 = out + r0g * EE + h * 64 + 2 * qc;
    float* d1 = d0 + 8 * EE;
    #pragma unroll
    for (int nt = 0; nt < 8; nt++) {
        float2 v0, v1;
        v0.x = o[nt][0] * i0; v0.y = o[nt][1] * i0;
        v1.x = o[nt][2] * i1; v1.y = o[nt][3] * i1;
        *(float2*)(d0 + nt * 8) = v0;
        *(float2*)(d1 + nt * 8) = v1;
    }
}

// ---------------------------------------------------------------------------
// Launch sequence
// ---------------------------------------------------------------------------
extern "C" void kernel_launch(void* const* d_in, const int* in_sizes, int n_in,
                              void* d_out, int out_size)
{
    const float* x         = (const float*)d_in[0];
    const float* ln1_w     = (const float*)d_in[1];
    const float* ln1_b     = (const float*)d_in[2];
    const float* ln2_w     = (const float*)d_in[3];
    const float* ln2_b     = (const float*)d_in[4];
    const float* in_proj_w = (const float*)d_in[5];
    const float* in_proj_b = (const float*)d_in[6];
    const float* out_w     = (const float*)d_in[7];
    const float* out_b     = (const float*)d_in[8];
    const float* w1        = (const float*)d_in[9];
    const float* b1        = (const float*)d_in[10];
    const float* w2        = (const float*)d_in[11];
    const float* b2        = (const float*)d_in[12];
    float* outp            = (float*)d_out;

    float *h, *qkv, *attn, *x2, *ffn;
    cudaGetSymbolAddress((void**)&h,    g_h);
    cudaGetSymbolAddress((void**)&qkv,  g_qkv);
    cudaGetSymbolAddress((void**)&attn, g_attn);
    cudaGetSymbolAddress((void**)&x2,   g_x2);
    cudaGetSymbolAddress((void**)&ffn,  g_ffn);

    cudaFuncSetAttribute(gemm_mma<EPI_NONE>, cudaFuncAttributeMaxDynamicSharedMemorySize, DSMEM_SZ);
    cudaFuncSetAttribute(gemm_mma<EPI_GELU>, cudaFuncAttributeMaxDynamicSharedMemorySize, DSMEM_SZ);
    cudaFuncSetAttribute(gemm_mma<EPI_RES>,  cudaFuncAttributeMaxDynamicSharedMemorySize, DSMEM_SZ);
    cudaFuncSetAttribute(attn_mma, cudaFuncAttributeMaxDynamicSharedMemorySize, ATTN_SMEM);

    // 1. h = LN1(x)
    ln_kernel<<<MM, 256>>>(x, ln1_w, ln1_b, h);
    // 2. qkv = h @ in_proj_w^T + b                    [16384, 3072]
    gemm_mma<EPI_NONE><<<dim3(3 * EE / 128, MM / 128), 256, DSMEM_SZ>>>(
        h, in_proj_w, in_proj_b, nullptr, qkv, 3 * EE, EE);
    // 3. attention
    attn_mma<<<dim3(SS / 64, BB * HH), 128, ATTN_SMEM>>>(qkv, attn);
    // 4. x2 = x + attn @ out_w^T + out_b
    gemm_mma<EPI_RES><<<dim3(EE / 128, MM / 128), 256, DSMEM_SZ>>>(
        attn, out_w, out_b, x, x2, EE, EE);
    // 5. h = LN2(x2)
    ln_kernel<<<MM, 256>>>(x2, ln2_w, ln2_b, h);
    // 6. ffn = gelu(h @ w1^T + b1)                    [16384, 4096]
    gemm_mma<EPI_GELU><<<dim3(FFN / 128, MM / 128), 256, DSMEM_SZ>>>(
        h, w1, b1, nullptr, ffn, FFN, EE);
    // 7. out = x2 + ffn @ w2^T + b2
    gemm_mma<EPI_RES><<<dim3(EE / 128, MM / 128), 256, DSMEM_SZ>>>(
        ffn, w2, b2, x2, outp, EE, FFN);
}

// round 9
// speedup vs baseline: 3.9712x; 1.0674x over previous
#include <cuda_runtime.h>
#include <cuda_bf16.h>
#include <math.h>
#include <stdint.h>

// ---------------------------------------------------------------------------
// Problem constants
// ---------------------------------------------------------------------------
#define BB   16
#define SS   1024
#define EE   1024
#define HH   16
#define HD   64
#define FFN  4096
#define MM   (BB * SS)          // 16384 rows

// ---------------------------------------------------------------------------
// Scratch buffers (device globals: allocation-free, graph-capture safe)
// ---------------------------------------------------------------------------
__device__ float g_h   [(size_t)MM * EE];
__device__ float g_qkv [(size_t)MM * 3 * EE];
__device__ float g_attn[(size_t)MM * EE];
__device__ float g_x2  [(size_t)MM * EE];
__device__ float g_ffn [(size_t)MM * FFN];
// pre-rounded tf32 weights
__device__ float g_wq  [(size_t)3 * EE * EE];
__device__ float g_wo  [(size_t)EE * EE];
__device__ float g_w1  [(size_t)FFN * EE];
__device__ float g_w2  [(size_t)EE * FFN];

// ---------------------------------------------------------------------------
// PTX helpers (sm_100 plain target: cp.async + mma.sync only)
// ---------------------------------------------------------------------------
__device__ __forceinline__ uint32_t smem_u32(const void* p) {
    uint32_t a;
    asm("{ .reg .u64 t; cvta.to.shared.u64 t, %1; cvt.u32.u64 %0, t; }"
        : "=r"(a) : "l"(p));
    return a;
}

__device__ __forceinline__ void cp_async16(uint32_t dst, const void* src) {
    asm volatile("cp.async.cg.shared.global [%0], [%1], 16;"
                 :: "r"(dst), "l"(src) : "memory");
}
#define CP_COMMIT() asm volatile("cp.async.commit_group;" ::: "memory")
#define CP_WAIT(n)  asm volatile("cp.async.wait_group %0;" :: "n"(n) : "memory")

// round-to-nearest fp32 -> tf32 (producers only; hot loops load raw bits)
__device__ __forceinline__ uint32_t f2tf(float x) {
    uint32_t r;
    asm("cvt.rna.tf32.f32 %0, %1;" : "=r"(r) : "f"(x));
    return r;
}
__device__ __forceinline__ float tf32r(float x) {
    return __uint_as_float(f2tf(x));
}

#define MMA_TF32(c, a, b) \
    asm volatile("mma.sync.aligned.m16n8k8.row.col.f32.tf32.tf32.f32 " \
        "{%0,%1,%2,%3}, {%4,%5,%6,%7}, {%8,%9}, {%0,%1,%2,%3};" \
        : "+f"((c)[0]), "+f"((c)[1]), "+f"((c)[2]), "+f"((c)[3]) \
        : "r"((a)[0]), "r"((a)[1]), "r"((a)[2]), "r"((a)[3]), \
          "r"((b)[0]), "r"((b)[1]))

// ---------------------------------------------------------------------------
// Weight pre-rounding: dst[i] = tf32(src[i]), vectorized
// ---------------------------------------------------------------------------
__global__ __launch_bounds__(256)
void tf32_cast(const float* __restrict__ s, float* __restrict__ d, int n4)
{
    const int i = blockIdx.x * 256 + threadIdx.x;
    if (i < n4) {
        float4 v = ((const float4*)s)[i];
        v.x = tf32r(v.x); v.y = tf32r(v.y);
        v.z = tf32r(v.z); v.w = tf32r(v.w);
        ((float4*)d)[i] = v;
    }
}

// ---------------------------------------------------------------------------
// tf32 mma.sync GEMM: C[M,N] = A[M,K] @ W[N,K]^T + bias (+gelu / +residual)
//   A and W are PRE-ROUNDED to tf32 -> raw fragment loads, no CVT in loop.
//   128x128 CTA tile, BK=32, 8 warps (2x4), warp tile 64x32,
//   3-stage cp.async pipeline, XOR-swizzled smem (32KB/stage -> 2 CTA/SM).
// ---------------------------------------------------------------------------
#define EPI_NONE 0
#define EPI_GELU 1
#define EPI_RES  2

#define GBK       32
#define GSTAGES   3
#define STAGE_FLT (2 * 128 * 32)              // A block then B block (floats)
#define DSMEM_SZ  (GSTAGES * STAGE_FLT * 4)   // 98304 bytes

// logical (row r, float col w in 0..31) -> physical float index (XOR swizzle)
#define SWIDX(r, w) \
    (((r) << 5) + (((((w) >> 2) ^ ((r) & 7)) << 2) | ((w) & 3)))

template<int EPI, bool RND>
__global__ __launch_bounds__(256, 2)
void gemm_mma(const float* __restrict__ A, const float* __restrict__ W,
              const float* __restrict__ bias, const float* __restrict__ Res,
              float* __restrict__ C, int N, int K)
{
    extern __shared__ float sm[];
    const uint32_t smA = smem_u32(sm);

    const int tid  = threadIdx.x;
    const int bm   = blockIdx.y * 128;
    const int bn   = blockIdx.x * 128;
    const int warp = tid >> 5, lane = tid & 31;
    const int wm   = (warp >> 2) * 64;        // 0,64
    const int wn   = (warp & 3) * 32;         // 0,32,64,96
    const int qr   = lane >> 2;               // 0..7
    const int qc   = lane & 3;                // 0..3

    float acc[4][4][4];
    #pragma unroll
    for (int i = 0; i < 4; i++)
        #pragma unroll
        for (int j = 0; j < 4; j++)
            #pragma unroll
            for (int k = 0; k < 4; k++) acc[i][j][k] = 0.f;

    // cp.async mapping: thread -> row tid>>1, chunk base (tid&1)*4, 4 x 16B
    const int  lrow = tid >> 1;
    const int  cb   = (tid & 1) * 4;
    const float* Ap = A + (long)(bm + lrow) * K;
    const float* Wp = W + (long)(bn + lrow) * K;
    const uint32_t dA = smA + lrow * 128;
    const uint32_t dB = smA + (128 + lrow) * 128;
    const int rx = lrow & 7;

    const int T = K / GBK;

    // prologue: stages 0,1
    #pragma unroll
    for (int u = 0; u < 2; ++u) {
        const uint32_t sb = u * (STAGE_FLT * 4);
        #pragma unroll
        for (int j = 0; j < 4; j++) {
            const int c = cb + j;
            const uint32_t so = ((c ^ rx) << 4);
            cp_async16(dA + sb + so, Ap + (long)u * GBK + c * 4);
            cp_async16(dB + sb + so, Wp + (long)u * GBK + c * 4);
        }
        CP_COMMIT();
    }

    for (int t = 0; t < T; ++t) {
        if (t + 2 < T) {
            const int u = t + 2;
            const uint32_t sb = (u % GSTAGES) * (STAGE_FLT * 4);
            #pragma unroll
            for (int j = 0; j < 4; j++) {
                const int c = cb + j;
                const uint32_t so = ((c ^ rx) << 4);
                cp_async16(dA + sb + so, Ap + (long)u * GBK + c * 4);
                cp_async16(dB + sb + so, Wp + (long)u * GBK + c * 4);
            }
        }
        CP_COMMIT();
        CP_WAIT(2);
        __syncthreads();

        const uint32_t* As = (const uint32_t*)(sm + (t % GSTAGES) * STAGE_FLT);
        const uint32_t* Bs = As + 128 * 32;

        #pragma unroll
        for (int ks = 0; ks < 4; ++ks) {
            uint32_t a[4][4], b[4][2];
            #pragma unroll
            for (int mt = 0; mt < 4; ++mt) {
                const int r0 = wm + mt * 16 + qr, r1 = r0 + 8;
                a[mt][0] = As[SWIDX(r0, ks * 8 + qc)];
                a[mt][1] = As[SWIDX(r1, ks * 8 + qc)];
                a[mt][2] = As[SWIDX(r0, ks * 8 + qc + 4)];
                a[mt][3] = As[SWIDX(r1, ks * 8 + qc + 4)];
            }
            #pragma unroll
            for (int nt = 0; nt < 4; ++nt) {
                const int r = wn + nt * 8 + qr;
                b[nt][0] = Bs[SWIDX(r, ks * 8 + qc)];
                b[nt][1] = Bs[SWIDX(r, ks * 8 + qc + 4)];
            }
            #pragma unroll
            for (int mt = 0; mt < 4; ++mt)
                #pragma unroll
                for (int nt = 0; nt < 4; ++nt)
                    MMA_TF32(acc[mt][nt], a[mt], b[nt]);
        }
        __syncthreads();
    }

    // epilogue
    #pragma unroll
    for (int mt = 0; mt < 4; ++mt) {
        #pragma unroll
        for (int r2 = 0; r2 < 2; ++r2) {
            const long row = bm + wm + mt * 16 + qr + r2 * 8;
            float* Crow = C + row * (long)N + bn;
            const float* Rrow = (EPI == EPI_RES) ? (Res + row * (long)N + bn)
                                                 : (const float*)nullptr;
            #pragma unroll
            for (int nt = 0; nt < 4; ++nt) {
                const int col = wn + nt * 8 + qc * 2;
                float2 v;
                v.x = acc[mt][nt][r2 * 2 + 0];
                v.y = acc[mt][nt][r2 * 2 + 1];
                const float2 bv = *(const float2*)(bias + bn + col);
                v.x += bv.x; v.y += bv.y;
                if (EPI == EPI_GELU) {
                    v.x = 0.5f * v.x * (1.0f + erff(v.x * 0.7071067811865475f));
                    v.y = 0.5f * v.y * (1.0f + erff(v.y * 0.7071067811865475f));
                }
                if (EPI == EPI_RES) {
                    const float2 rv = *(const float2*)(Rrow + col);
                    v.x += rv.x; v.y += rv.y;
                }
                if (RND) { v.x = tf32r(v.x); v.y = tf32r(v.y); }
                *(float2*)(Crow + col) = v;
            }
        }
    }
}

// ---------------------------------------------------------------------------
// LayerNorm: output rounded to tf32 (consumed only as GEMM A operand)
// ---------------------------------------------------------------------------
__global__ __launch_bounds__(256)
void ln_kernel(const float* __restrict__ x, const float* __restrict__ w,
               const float* __restrict__ b, float* __restrict__ y)
{
    const long row = blockIdx.x;
    const float4* xr = (const float4*)(x + (row << 10));
    float4 xv = xr[threadIdx.x];

    float s  = xv.x + xv.y + xv.z + xv.w;
    float sq = xv.x * xv.x + xv.y * xv.y + xv.z * xv.z + xv.w * xv.w;
    #pragma unroll
    for (int o = 16; o; o >>= 1) {
        s  += __shfl_xor_sync(0xffffffffu, s,  o);
        sq += __shfl_xor_sync(0xffffffffu, sq, o);
    }
    __shared__ float ss[8], ssq[8];
    __shared__ float mu_s, rstd_s;
    const int warp = threadIdx.x >> 5, lane = threadIdx.x & 31;
    if (lane == 0) { ss[warp] = s; ssq[warp] = sq; }
    __syncthreads();
    if (threadIdx.x == 0) {
        float S = 0.f, SQ = 0.f;
        #pragma unroll
        for (int i = 0; i < 8; i++) { S += ss[i]; SQ += ssq[i]; }
        const float mu  = S * (1.0f / 1024.0f);
        const float var = SQ * (1.0f / 1024.0f) - mu * mu;
        mu_s   = mu;
        rstd_s = rsqrtf(var + 1e-6f);
    }
    __syncthreads();
    const float mu = mu_s, rstd = rstd_s;

    const float4 wv = ((const float4*)w)[threadIdx.x];
    const float4 bv = ((const float4*)b)[threadIdx.x];
    float4 o;
    o.x = tf32r((xv.x - mu) * rstd * wv.x + bv.x);
    o.y = tf32r((xv.y - mu) * rstd * wv.y + bv.y);
    o.z = tf32r((xv.z - mu) * rstd * wv.z + bv.z);
    o.w = tf32r((xv.w - mu) * rstd * wv.w + bv.w);
    ((float4*)(y + (row << 10)))[threadIdx.x] = o;
}

// ---------------------------------------------------------------------------
// Flash attention with tf32 mma.sync.
//   qkv is pre-rounded tf32 -> raw fragment loads everywhere.
//   Output rounded to tf32 (consumed only by out-proj GEMM).
// ---------------------------------------------------------------------------
#define AQ_STR 68
#define AK_STR 68
#define AV_STR 72
#define AP_STR 36
#define AQ_FLT (64 * AQ_STR)              // 4352
#define AK_FLT (2 * 32 * AK_STR)          // 4352
#define AV_FLT (2 * 32 * AV_STR)          // 4608
#define AP_FLT (64 * AP_STR)              // 2304
#define ATTN_SMEM ((AQ_FLT + AK_FLT + AV_FLT + AP_FLT) * 4)  // 62464 B

__global__ __launch_bounds__(128)
void attn_mma(const float* __restrict__ qkv, float* __restrict__ out)
{
    extern __shared__ float asmem[];
    float* Qs = asmem;
    float* Ks = Qs + AQ_FLT;
    float* Vs = Ks + AK_FLT;
    float* Ps = Vs + AV_FLT;

    const int tid  = threadIdx.x;
    const int warp = tid >> 5, lane = tid & 31;
    const int qr   = lane >> 2, qc = lane & 3;
    const int b    = blockIdx.y >> 4, h = blockIdx.y & 15;
    const int q0   = blockIdx.x * 64;
    const int wm   = warp * 16;
    const long base = (long)b * SS * 3072 + h * 64;

    const uint32_t sQ = smem_u32(Qs), sK = smem_u32(Ks), sV = smem_u32(Vs);

    // Q tile (64 rows x 64 floats = 1024 16B-chunks): 8 per thread
    #pragma unroll
    for (int i = 0; i < 8; i++) {
        const int cc = tid + i * 128;
        const int row = cc >> 4, c = cc & 15;    // 16 chunks per row
        cp_async16(sQ + (row * AQ_STR + c * 4) * 4,
                   qkv + base + (long)(q0 + row) * 3072 + c * 4);
    }
    // K/V tile kt=0 (32 rows x 64 floats = 512 chunks each): 4 per thread each
    #pragma unroll
    for (int i = 0; i < 4; i++) {
        const int cc = tid + i * 128;
        const int row = cc >> 4, c = cc & 15;
        const long ko = base + 1024 + (long)row * 3072 + c * 4;
        cp_async16(sK + (row * AK_STR + c * 4) * 4, qkv + ko);
        cp_async16(sV + (row * AV_STR + c * 4) * 4, qkv + ko + 1024);
    }
    CP_COMMIT();
    CP_WAIT(0);
    __syncthreads();

    // Q fragments: x0.125 is exact (power of 2) on already-tf32 values
    uint32_t qa[8][4];
    {
        const int r0 = wm + qr, r1 = r0 + 8;
        #pragma unroll
        for (int ks = 0; ks < 8; ks++) {
            qa[ks][0] = __float_as_uint(Qs[r0 * AQ_STR + ks * 8 + qc] * 0.125f);
            qa[ks][1] = __float_as_uint(Qs[r1 * AQ_STR + ks * 8 + qc] * 0.125f);
            qa[ks][2] = __float_as_uint(Qs[r0 * AQ_STR + ks * 8 + qc + 4] * 0.125f);
            qa[ks][3] = __float_as_uint(Qs[r1 * AQ_STR + ks * 8 + qc + 4] * 0.125f);
        }
    }

    float o[8][4];
    #pragma unroll
    for (int nt = 0; nt < 8; nt++)
        #pragma unroll
        for (int k = 0; k < 4; k++) o[nt][k] = 0.f;
    float mrow0 = -1e30f, mrow1 = -1e30f, l0 = 0.f, l1 = 0.f;

    for (int kt = 0; kt < 32; kt++) {
        const int cur = kt & 1;
        __syncthreads();                       // all warps done with buf cur^1
        if (kt + 1 < 32) {
            const int nxt = cur ^ 1;
            #pragma unroll
            for (int i = 0; i < 4; i++) {
                const int cc = tid + i * 128;
                const int row = cc >> 4, c = cc & 15;
                const long ko = base + 1024
                              + (long)((kt + 1) * 32 + row) * 3072 + c * 4;
                cp_async16(sK + ((nxt * 32 + row) * AK_STR + c * 4) * 4, qkv + ko);
                cp_async16(sV + ((nxt * 32 + row) * AV_STR + c * 4) * 4, qkv + ko + 1024);
            }
        }
        CP_COMMIT();
        CP_WAIT(1);
        __syncthreads();

        const float* Kc = Ks + cur * 32 * AK_STR;
        const float* Vc = Vs + cur * 32 * AV_STR;

        // S = (Q/8) K^T  (warp tile 16 x 32 keys)
        float s[4][4];
        #pragma unroll
        for (int nt = 0; nt < 4; nt++)
            #pragma unroll
            for (int k = 0; k < 4; k++) s[nt][k] = 0.f;
        #pragma unroll
        for (int ks = 0; ks < 8; ks++) {
            uint32_t bf[4][2];
            #pragma unroll
            for (int nt = 0; nt < 4; nt++) {
                const float* p = Kc + (nt * 8 + qr) * AK_STR + ks * 8 + qc;
                bf[nt][0] = __float_as_uint(p[0]);
                bf[nt][1] = __float_as_uint(p[4]);
            }
            #pragma unroll
            for (int nt = 0; nt < 4; nt++)
                MMA_TF32(s[nt], qa[ks], bf[nt]);
        }

        // online softmax (rows r0 = wm+qr, r1 = wm+qr+8; quad owns each row)
        float m0 = -1e30f, m1 = -1e30f;
        #pragma unroll
        for (int nt = 0; nt < 4; nt++) {
            m0 = fmaxf(m0, fmaxf(s[nt][0], s[nt][1]));
            m1 = fmaxf(m1, fmaxf(s[nt][2], s[nt][3]));
        }
        m0 = fmaxf(m0, __shfl_xor_sync(0xffffffffu, m0, 1));
        m0 = fmaxf(m0, __shfl_xor_sync(0xffffffffu, m0, 2));
        m1 = fmaxf(m1, __shfl_xor_sync(0xffffffffu, m1, 1));
        m1 = fmaxf(m1, __shfl_xor_sync(0xffffffffu, m1, 2));
        const float n0 = fmaxf(mrow0, m0), n1 = fmaxf(mrow1, m1);
        const float c0 = __expf(mrow0 - n0), c1 = __expf(mrow1 - n1);
        float ps0 = 0.f, ps1 = 0.f;
        float* P0 = Ps + (wm + qr) * AP_STR + 2 * qc;
        float* P1 = Ps + (wm + qr + 8) * AP_STR + 2 * qc;
        #pragma unroll
        for (int nt = 0; nt < 4; nt++) {
            const float p00 = __expf(s[nt][0] - n0);
            const float p01 = __expf(s[nt][1] - n0);
            const float p10 = __expf(s[nt][2] - n1);
            const float p11 = __expf(s[nt][3] - n1);
            ps0 += p00 + p01;
            ps1 += p10 + p11;
            P0[nt * 8 + 0] = __uint_as_float(f2tf(p00));
            P0[nt * 8 + 1] = __uint_as_float(f2tf(p01));
            P1[nt * 8 + 0] = __uint_as_float(f2tf(p10));
            P1[nt * 8 + 1] = __uint_as_float(f2tf(p11));
        }
        ps0 += __shfl_xor_sync(0xffffffffu, ps0, 1);
        ps0 += __shfl_xor_sync(0xffffffffu, ps0, 2);
        ps1 += __shfl_xor_sync(0xffffffffu, ps1, 1);
        ps1 += __shfl_xor_sync(0xffffffffu, ps1, 2);
        l0 = l0 * c0 + ps0;
        l1 = l1 * c1 + ps1;
        mrow0 = n0; mrow1 = n1;
        #pragma unroll
        for (int nt = 0; nt < 8; nt++) {
            o[nt][0] *= c0; o[nt][1] *= c0;
            o[nt][2] *= c1; o[nt][3] *= c1;
        }
        __syncwarp();                          // P visible within warp

        // O += P V  (k = 32 keys, n = 64 hd); V already tf32 -> raw loads
        #pragma unroll
        for (int ks2 = 0; ks2 < 4; ks2++) {
            uint32_t pa[4];
            pa[0] = __float_as_uint(Ps[(wm + qr) * AP_STR + ks2 * 8 + qc]);
            pa[1] = __float_as_uint(Ps[(wm + qr + 8) * AP_STR + ks2 * 8 + qc]);
            pa[2] = __float_as_uint(Ps[(wm + qr) * AP_STR + ks2 * 8 + qc + 4]);
            pa[3] = __float_as_uint(Ps[(wm + qr + 8) * AP_STR + ks2 * 8 + qc + 4]);
            #pragma unroll
            for (int nt = 0; nt < 8; nt++) {
                uint32_t bv[2];
                bv[0] = __float_as_uint(Vc[(ks2 * 8 + qc) * AV_STR + nt * 8 + qr]);
                bv[1] = __float_as_uint(Vc[(ks2 * 8 + qc + 4) * AV_STR + nt * 8 + qr]);
                MMA_TF32(o[nt], pa, bv);
            }
        }
        __syncwarp();                          // P reads done before next write
    }

    const float i0 = 1.0f / l0, i1 = 1.0f / l1;
    const long r0g = (long)(b * SS + q0 + wm + qr);
    float* d0 = out + r0g * EE + h * 64 + 2 * qc;
    float* d1 = d0 + 8 * EE;
    #pragma unroll
    for (int nt = 0; nt < 8; nt++) {
        float2 v0, v1;
        v0.x = tf32r(o[nt][0] * i0); v0.y = tf32r(o[nt][1] * i0);
        v1.x = tf32r(o[nt][2] * i1); v1.y = tf32r(o[nt][3] * i1);
        *(float2*)(d0 + nt * 8) = v0;
        *(float2*)(d1 + nt * 8) = v1;
    }
}

// ---------------------------------------------------------------------------
// Launch sequence
// ---------------------------------------------------------------------------
extern "C" void kernel_launch(void* const* d_in, const int* in_sizes, int n_in,
                              void* d_out, int out_size)
{
    const float* x         = (const float*)d_in[0];
    const float* ln1_w     = (const float*)d_in[1];
    const float* ln1_b     = (const float*)d_in[2];
    const float* ln2_w     = (const float*)d_in[3];
    const float* ln2_b     = (const float*)d_in[4];
    const float* in_proj_w = (const float*)d_in[5];
    const float* in_proj_b = (const float*)d_in[6];
    const float* out_w     = (const float*)d_in[7];
    const float* out_b     = (const float*)d_in[8];
    const float* w1        = (const float*)d_in[9];
    const float* b1        = (const float*)d_in[10];
    const float* w2        = (const float*)d_in[11];
    const float* b2        = (const float*)d_in[12];
    float* outp            = (float*)d_out;

    float *h, *qkv, *attn, *x2, *ffn, *wq, *wo, *w1t, *w2t;
    cudaGetSymbolAddress((void**)&h,    g_h);
    cudaGetSymbolAddress((void**)&qkv,  g_qkv);
    cudaGetSymbolAddress((void**)&attn, g_attn);
    cudaGetSymbolAddress((void**)&x2,   g_x2);
    cudaGetSymbolAddress((void**)&ffn,  g_ffn);
    cudaGetSymbolAddress((void**)&wq,   g_wq);
    cudaGetSymbolAddress((void**)&wo,   g_wo);
    cudaGetSymbolAddress((void**)&w1t,  g_w1);
    cudaGetSymbolAddress((void**)&w2t,  g_w2);

    cudaFuncSetAttribute(gemm_mma<EPI_NONE, true>,  cudaFuncAttributeMaxDynamicSharedMemorySize, DSMEM_SZ);
    cudaFuncSetAttribute(gemm_mma<EPI_GELU, true>,  cudaFuncAttributeMaxDynamicSharedMemorySize, DSMEM_SZ);
    cudaFuncSetAttribute(gemm_mma<EPI_RES,  false>, cudaFuncAttributeMaxDynamicSharedMemorySize, DSMEM_SZ);
    cudaFuncSetAttribute(attn_mma, cudaFuncAttributeMaxDynamicSharedMemorySize, ATTN_SMEM);

    // 0. pre-round weights to tf32 (HBM-bound, ~30us total)
    tf32_cast<<<(3 * EE * EE / 4 + 255) / 256, 256>>>(in_proj_w, wq, 3 * EE * EE / 4);
    tf32_cast<<<(EE * EE / 4 + 255) / 256, 256>>>(out_w, wo, EE * EE / 4);
    tf32_cast<<<(FFN * EE / 4 + 255) / 256, 256>>>(w1, w1t, FFN * EE / 4);
    tf32_cast<<<(EE * FFN / 4 + 255) / 256, 256>>>(w2, w2t, EE * FFN / 4);

    // 1. h = tf32(LN1(x))
    ln_kernel<<<MM, 256>>>(x, ln1_w, ln1_b, h);
    // 2. qkv = tf32(h @ wq^T + b)                     [16384, 3072]
    gemm_mma<EPI_NONE, true><<<dim3(3 * EE / 128, MM / 128), 256, DSMEM_SZ>>>(
        h, wq, in_proj_b, nullptr, qkv, 3 * EE, EE);
    // 3. attention (tf32 in, tf32-rounded out)
    attn_mma<<<dim3(SS / 64, BB * HH), 128, ATTN_SMEM>>>(qkv, attn);
    // 4. x2 = x + attn @ wo^T + out_b                 (full fp32)
    gemm_mma<EPI_RES, false><<<dim3(EE / 128, MM / 128), 256, DSMEM_SZ>>>(
        attn, wo, out_b, x, x2, EE, EE);
    // 5. h = tf32(LN2(x2))
    ln_kernel<<<MM, 256>>>(x2, ln2_w, ln2_b, h);
    // 6. ffn = tf32(gelu(h @ w1^T + b1))              [16384, 4096]
    gemm_mma<EPI_GELU, true><<<dim3(FFN / 128, MM / 128), 256, DSMEM_SZ>>>(
        h, w1t, b1, nullptr, ffn, FFN, EE);
    // 7. out = x2 + ffn @ w2^T + b2                   (full fp32)
    gemm_mma<EPI_RES, false><<<dim3(EE / 128, MM / 128), 256, DSMEM_SZ>>>(
        ffn, w2t, b2, x2, outp, EE, FFN);
}

// round 12
// speedup vs baseline: 4.3339x; 1.0913x over previous
#include <cuda_runtime.h>
#include <cuda_bf16.h>
#include <math.h>
#include <stdint.h>

// ---------------------------------------------------------------------------
// Problem constants
// ---------------------------------------------------------------------------
#define BB   16
#define SS   1024
#define EE   1024
#define HH   16
#define HD   64
#define FFN  4096
#define MM   (BB * SS)          // 16384 rows

// ---------------------------------------------------------------------------
// Scratch buffers (device globals: allocation-free, graph-capture safe)
// ---------------------------------------------------------------------------
__device__ float g_h   [(size_t)MM * EE];
__device__ float g_qkv [(size_t)MM * 3 * EE];
__device__ float g_attn[(size_t)MM * EE];
__device__ float g_x2  [(size_t)MM * EE];
__device__ float g_ffn [(size_t)MM * FFN];
// pre-rounded tf32 weights
__device__ float g_wq  [(size_t)3 * EE * EE];
__device__ float g_wo  [(size_t)EE * EE];
__device__ float g_w1  [(size_t)FFN * EE];
__device__ float g_w2  [(size_t)EE * FFN];

// ---------------------------------------------------------------------------
// PTX helpers (sm_100 plain target: cp.async + mma.sync + ldmatrix)
// ---------------------------------------------------------------------------
__device__ __forceinline__ uint32_t smem_u32(const void* p) {
    uint32_t a;
    asm("{ .reg .u64 t; cvta.to.shared.u64 t, %1; cvt.u32.u64 %0, t; }"
        : "=r"(a) : "l"(p));
    return a;
}

__device__ __forceinline__ void cp_async16(uint32_t dst, const void* src) {
    asm volatile("cp.async.cg.shared.global [%0], [%1], 16;"
                 :: "r"(dst), "l"(src) : "memory");
}
#define CP_COMMIT() asm volatile("cp.async.commit_group;" ::: "memory")
#define CP_WAIT(n)  asm volatile("cp.async.wait_group %0;" :: "n"(n) : "memory")

// round-to-nearest fp32 -> tf32 (producers only; hot loops load raw bits)
__device__ __forceinline__ uint32_t f2tf(float x) {
    uint32_t r;
    asm("cvt.rna.tf32.f32 %0, %1;" : "=r"(r) : "f"(x));
    return r;
}
__device__ __forceinline__ float tf32r(float x) {
    return __uint_as_float(f2tf(x));
}

#define MMA_TF32(c, a, b) \
    asm volatile("mma.sync.aligned.m16n8k8.row.col.f32.tf32.tf32.f32 " \
        "{%0,%1,%2,%3}, {%4,%5,%6,%7}, {%8,%9}, {%0,%1,%2,%3};" \
        : "+f"((c)[0]), "+f"((c)[1]), "+f"((c)[2]), "+f"((c)[3]) \
        : "r"((a)[0]), "r"((a)[1]), "r"((a)[2]), "r"((a)[3]), \
          "r"((b)[0]), "r"((b)[1]))

// ldmatrix: 8x8 b16 matrices; for tf32 an 8row x 8tf32col block = 2 matrices.
// x4 yields exactly the m16n8k8 A fragment {a0,a1,a2,a3}; x2 the B fragment.
#define LDSM_X4(r, addr) \
    asm volatile("ldmatrix.sync.aligned.m8n8.x4.shared.b16 {%0,%1,%2,%3}, [%4];" \
        : "=r"((r)[0]), "=r"((r)[1]), "=r"((r)[2]), "=r"((r)[3]) : "r"(addr))
#define LDSM_X2(r, addr) \
    asm volatile("ldmatrix.sync.aligned.m8n8.x2.shared.b16 {%0,%1}, [%2];" \
        : "=r"((r)[0]), "=r"((r)[1]) : "r"(addr))

// ---------------------------------------------------------------------------
// Weight pre-rounding: dst[i] = tf32(src[i]), vectorized
// ---------------------------------------------------------------------------
__global__ __launch_bounds__(256)
void tf32_cast(const float* __restrict__ s, float* __restrict__ d, int n4)
{
    const int i = blockIdx.x * 256 + threadIdx.x;
    if (i < n4) {
        float4 v = ((const float4*)s)[i];
        v.x = tf32r(v.x); v.y = tf32r(v.y);
        v.z = tf32r(v.z); v.w = tf32r(v.w);
        ((float4*)d)[i] = v;
    }
}

// ---------------------------------------------------------------------------
// tf32 mma.sync GEMM: C[M,N] = A[M,K] @ W[N,K]^T + bias (+gelu / +residual)
//   A and W pre-rounded tf32; fragments via ldmatrix (8 LDSM per 16 MMA).
//   128x128 CTA tile, BK=32, 8 warps (2x4), warp tile 64x32,
//   3-stage cp.async pipeline, XOR-swizzled smem (32KB/stage -> 2 CTA/SM).
// ---------------------------------------------------------------------------
#define EPI_NONE 0
#define EPI_GELU 1
#define EPI_RES  2

#define GBK       32
#define GSTAGES   3
#define STAGE_FLT (2 * 128 * 32)              // A block then B block (floats)
#define STAGE_B   (STAGE_FLT * 4)
#define ABLK_B    (128 * 32 * 4)              // 16384 bytes
#define DSMEM_SZ  (GSTAGES * STAGE_B)         // 98304 bytes

// logical (row r, float col w in 0..31) -> physical float index (XOR swizzle)
#define SWIDX(r, w) \
    (((r) << 5) + (((((w) >> 2) ^ ((r) & 7)) << 2) | ((w) & 3)))

template<int EPI, bool RND>
__global__ __launch_bounds__(256, 2)
void gemm_mma(const float* __restrict__ A, const float* __restrict__ W,
              const float* __restrict__ bias, const float* __restrict__ Res,
              float* __restrict__ C, int N, int K)
{
    extern __shared__ float sm[];
    const uint32_t smA = smem_u32(sm);

    const int tid  = threadIdx.x;
    const int bm   = blockIdx.y * 128;
    const int bn   = blockIdx.x * 128;
    const int warp = tid >> 5, lane = tid & 31;
    const int wm   = (warp >> 2) * 64;        // 0,64
    const int wn   = (warp & 3) * 32;         // 0,32,64,96
    const int qr   = lane >> 2;               // 0..7
    const int qc   = lane & 3;                // 0..3
    const int lx   = lane & 7;

    // per-lane ldmatrix row bases (bytes, stage-relative)
    const uint32_t aRow = (uint32_t)(wm + (lane & 15)) << 7;          // row*128B
    const uint32_t aBit = (uint32_t)(lane >> 4);                      // col-half
    const uint32_t bRow = (uint32_t)(wn + lx) << 7;
    const uint32_t bBit = (uint32_t)((lane >> 3) & 1);

    float acc[4][4][4];
    #pragma unroll
    for (int i = 0; i < 4; i++)
        #pragma unroll
        for (int j = 0; j < 4; j++)
            #pragma unroll
            for (int k = 0; k < 4; k++) acc[i][j][k] = 0.f;

    // cp.async mapping: thread -> row tid>>1, chunk base (tid&1)*4, 4 x 16B
    const int  lrow = tid >> 1;
    const int  cb   = (tid & 1) * 4;
    const float* Ap = A + (long)(bm + lrow) * K;
    const float* Wp = W + (long)(bn + lrow) * K;
    const uint32_t dA = smA + lrow * 128;
    const uint32_t dB = smA + ABLK_B + lrow * 128;
    const int rx = lrow & 7;

    const int T = K / GBK;

    // prologue: stages 0,1
    #pragma unroll
    for (int u = 0; u < 2; ++u) {
        const uint32_t sb = u * STAGE_B;
        #pragma unroll
        for (int j = 0; j < 4; j++) {
            const int c = cb + j;
            const uint32_t so = ((c ^ rx) << 4);
            cp_async16(dA + sb + so, Ap + (long)u * GBK + c * 4);
            cp_async16(dB + sb + so, Wp + (long)u * GBK + c * 4);
        }
        CP_COMMIT();
    }

    for (int t = 0; t < T; ++t) {
        if (t + 2 < T) {
            const int u = t + 2;
            const uint32_t sb = (u % GSTAGES) * STAGE_B;
            #pragma unroll
            for (int j = 0; j < 4; j++) {
                const int c = cb + j;
                const uint32_t so = ((c ^ rx) << 4);
                cp_async16(dA + sb + so, Ap + (long)u * GBK + c * 4);
                cp_async16(dB + sb + so, Wp + (long)u * GBK + c * 4);
            }
        }
        CP_COMMIT();
        CP_WAIT(2);
        __syncthreads();

        const uint32_t stb = smA + (t % GSTAGES) * STAGE_B;

        #pragma unroll
        for (int ks = 0; ks < 4; ++ks) {
            uint32_t a[4][4], b[4][2];
            const uint32_t aAddr = stb + aRow
                                 + ((((uint32_t)(ks << 1) + aBit) ^ (aRow >> 7 & 7u)) << 4);
            const uint32_t bAddr = stb + ABLK_B + bRow
                                 + ((((uint32_t)(ks << 1) + bBit) ^ lx) << 4);
            #pragma unroll
            for (int mt = 0; mt < 4; ++mt)
                LDSM_X4(a[mt], aAddr + mt * 2048);
            #pragma unroll
            for (int nt = 0; nt < 4; ++nt)
                LDSM_X2(b[nt], bAddr + nt * 1024);
            #pragma unroll
            for (int mt = 0; mt < 4; ++mt)
                #pragma unroll
                for (int nt = 0; nt < 4; ++nt)
                    MMA_TF32(acc[mt][nt], a[mt], b[nt]);
        }
        __syncthreads();
    }

    // epilogue
    #pragma unroll
    for (int mt = 0; mt < 4; ++mt) {
        #pragma unroll
        for (int r2 = 0; r2 < 2; ++r2) {
            const long row = bm + wm + mt * 16 + qr + r2 * 8;
            float* Crow = C + row * (long)N + bn;
            const float* Rrow = (EPI == EPI_RES) ? (Res + row * (long)N + bn)
                                                 : (const float*)nullptr;
            #pragma unroll
            for (int nt = 0; nt < 4; ++nt) {
                const int col = wn + nt * 8 + qc * 2;
                float2 v;
                v.x = acc[mt][nt][r2 * 2 + 0];
                v.y = acc[mt][nt][r2 * 2 + 1];
                const float2 bv = *(const float2*)(bias + bn + col);
                v.x += bv.x; v.y += bv.y;
                if (EPI == EPI_GELU) {
                    v.x = 0.5f * v.x * (1.0f + erff(v.x * 0.7071067811865475f));
                    v.y = 0.5f * v.y * (1.0f + erff(v.y * 0.7071067811865475f));
                }
                if (EPI == EPI_RES) {
                    const float2 rv = *(const float2*)(Rrow + col);
                    v.x += rv.x; v.y += rv.y;
                }
                if (RND) { v.x = tf32r(v.x); v.y = tf32r(v.y); }
                *(float2*)(Crow + col) = v;
            }
        }
    }
}

// ---------------------------------------------------------------------------
// LayerNorm: output rounded to tf32 (consumed only as GEMM A operand)
// ---------------------------------------------------------------------------
__global__ __launch_bounds__(256)
void ln_kernel(const float* __restrict__ x, const float* __restrict__ w,
               const float* __restrict__ b, float* __restrict__ y)
{
    const long row = blockIdx.x;
    const float4* xr = (const float4*)(x + (row << 10));
    float4 xv = xr[threadIdx.x];

    float s  = xv.x + xv.y + xv.z + xv.w;
    float sq = xv.x * xv.x + xv.y * xv.y + xv.z * xv.z + xv.w * xv.w;
    #pragma unroll
    for (int o = 16; o; o >>= 1) {
        s  += __shfl_xor_sync(0xffffffffu, s,  o);
        sq += __shfl_xor_sync(0xffffffffu, sq, o);
    }
    __shared__ float ss[8], ssq[8];
    __shared__ float mu_s, rstd_s;
    const int warp = threadIdx.x >> 5, lane = threadIdx.x & 31;
    if (lane == 0) { ss[warp] = s; ssq[warp] = sq; }
    __syncthreads();
    if (threadIdx.x == 0) {
        float S = 0.f, SQ = 0.f;
        #pragma unroll
        for (int i = 0; i < 8; i++) { S += ss[i]; SQ += ssq[i]; }
        const float mu  = S * (1.0f / 1024.0f);
        const float var = SQ * (1.0f / 1024.0f) - mu * mu;
        mu_s   = mu;
        rstd_s = rsqrtf(var + 1e-6f);
    }
    __syncthreads();
    const float mu = mu_s, rstd = rstd_s;

    const float4 wv = ((const float4*)w)[threadIdx.x];
    const float4 bv = ((const float4*)b)[threadIdx.x];
    float4 o;
    o.x = tf32r((xv.x - mu) * rstd * wv.x + bv.x);
    o.y = tf32r((xv.y - mu) * rstd * wv.y + bv.y);
    o.z = tf32r((xv.z - mu) * rstd * wv.z + bv.z);
    o.w = tf32r((xv.w - mu) * rstd * wv.w + bv.w);
    ((float4*)(y + (row << 10)))[threadIdx.x] = o;
}

// ---------------------------------------------------------------------------
// Flash attention with tf32 mma.sync; K fragments via ldmatrix.
// ---------------------------------------------------------------------------
#define AQ_STR 68
#define AK_STR 68
#define AV_STR 72
#define AP_STR 36
#define AQ_FLT (64 * AQ_STR)              // 4352
#define AK_FLT (2 * 32 * AK_STR)          // 4352
#define AV_FLT (2 * 32 * AV_STR)          // 4608
#define AP_FLT (64 * AP_STR)              // 2304
#define ATTN_SMEM ((AQ_FLT + AK_FLT + AV_FLT + AP_FLT) * 4)  // 62464 B

__global__ __launch_bounds__(128)
void attn_mma(const float* __restrict__ qkv, float* __restrict__ out)
{
    extern __shared__ float asmem[];
    float* Qs = asmem;
    float* Ks = Qs + AQ_FLT;
    float* Vs = Ks + AK_FLT;
    float* Ps = Vs + AV_FLT;

    const int tid  = threadIdx.x;
    const int warp = tid >> 5, lane = tid & 31;
    const int qr   = lane >> 2, qc = lane & 3;
    const int lx   = lane & 7;
    const int b    = blockIdx.y >> 4, h = blockIdx.y & 15;
    const int q0   = blockIdx.x * 64;
    const int wm   = warp * 16;
    const long base = (long)b * SS * 3072 + h * 64;

    const uint32_t sQ = smem_u32(Qs), sK = smem_u32(Ks), sV = smem_u32(Vs);

    // Q tile (64 rows x 64 floats = 1024 16B-chunks): 8 per thread
    #pragma unroll
    for (int i = 0; i < 8; i++) {
        const int cc = tid + i * 128;
        const int row = cc >> 4, c = cc & 15;    // 16 chunks per row
        cp_async16(sQ + (row * AQ_STR + c * 4) * 4,
                   qkv + base + (long)(q0 + row) * 3072 + c * 4);
    }
    // K/V tile kt=0 (32 rows x 64 floats = 512 chunks each): 4 per thread each
    #pragma unroll
    for (int i = 0; i < 4; i++) {
        const int cc = tid + i * 128;
        const int row = cc >> 4, c = cc & 15;
        const long ko = base + 1024 + (long)row * 3072 + c * 4;
        cp_async16(sK + (row * AK_STR + c * 4) * 4, qkv + ko);
        cp_async16(sV + (row * AV_STR + c * 4) * 4, qkv + ko + 1024);
    }
    CP_COMMIT();
    CP_WAIT(0);
    __syncthreads();

    // Q fragments: x0.125 is exact (power of 2) on already-tf32 values
    uint32_t qa[8][4];
    {
        const int r0 = wm + qr, r1 = r0 + 8;
        #pragma unroll
        for (int ks = 0; ks < 8; ks++) {
            qa[ks][0] = __float_as_uint(Qs[r0 * AQ_STR + ks * 8 + qc] * 0.125f);
            qa[ks][1] = __float_as_uint(Qs[r1 * AQ_STR + ks * 8 + qc] * 0.125f);
            qa[ks][2] = __float_as_uint(Qs[r0 * AQ_STR + ks * 8 + qc + 4] * 0.125f);
            qa[ks][3] = __float_as_uint(Qs[r1 * AQ_STR + ks * 8 + qc + 4] * 0.125f);
        }
    }

    // ldmatrix per-lane row/half for K (B-operand pattern)
    const uint32_t kRowOff = (uint32_t)lx * (AK_STR * 4);   // row*272B
    const uint32_t kBit    = (uint32_t)((lane >> 3) & 1);

    float o[8][4];
    #pragma unroll
    for (int nt = 0; nt < 8; nt++)
        #pragma unroll
        for (int k = 0; k < 4; k++) o[nt][k] = 0.f;
    float mrow0 = -1e30f, mrow1 = -1e30f, l0 = 0.f, l1 = 0.f;

    for (int kt = 0; kt < 32; kt++) {
        const int cur = kt & 1;
        __syncthreads();                       // all warps done with buf cur^1
        if (kt + 1 < 32) {
            const int nxt = cur ^ 1;
            #pragma unroll
            for (int i = 0; i < 4; i++) {
                const int cc = tid + i * 128;
                const int row = cc >> 4, c = cc & 15;
                const long ko = base + 1024
                              + (long)((kt + 1) * 32 + row) * 3072 + c * 4;
                cp_async16(sK + ((nxt * 32 + row) * AK_STR + c * 4) * 4, qkv + ko);
                cp_async16(sV + ((nxt * 32 + row) * AV_STR + c * 4) * 4, qkv + ko + 1024);
            }
        }
        CP_COMMIT();
        CP_WAIT(1);
        __syncthreads();

        const uint32_t sKc = sK + cur * 32 * AK_STR * 4;
        const float*   Vc  = Vs + cur * 32 * AV_STR;

        // S = (Q/8) K^T  (warp tile 16 x 32 keys), K frags via ldmatrix.x2
        float s[4][4];
        #pragma unroll
        for (int nt = 0; nt < 4; nt++)
            #pragma unroll
            for (int k = 0; k < 4; k++) s[nt][k] = 0.f;
        #pragma unroll
        for (int ks = 0; ks < 8; ks++) {
            const uint32_t kAddr = sKc + kRowOff + (((uint32_t)(ks << 1) + kBit) << 4);
            uint32_t bf[4][2];
            #pragma unroll
            for (int nt = 0; nt < 4; nt++)
                LDSM_X2(bf[nt], kAddr + nt * (8 * AK_STR * 4));
            #pragma unroll
            for (int nt = 0; nt < 4; nt++)
                MMA_TF32(s[nt], qa[ks], bf[nt]);
        }

        // online softmax (rows r0 = wm+qr, r1 = wm+qr+8; quad owns each row)
        float m0 = -1e30f, m1 = -1e30f;
        #pragma unroll
        for (int nt = 0; nt < 4; nt++) {
            m0 = fmaxf(m0, fmaxf(s[nt][0], s[nt][1]));
            m1 = fmaxf(m1, fmaxf(s[nt][2], s[nt][3]));
        }
        m0 = fmaxf(m0, __shfl_xor_sync(0xffffffffu, m0, 1));
        m0 = fmaxf(m0, __shfl_xor_sync(0xffffffffu, m0, 2));
        m1 = fmaxf(m1, __shfl_xor_sync(0xffffffffu, m1, 1));
        m1 = fmaxf(m1, __shfl_xor_sync(0xffffffffu, m1, 2));
        const float n0 = fmaxf(mrow0, m0), n1 = fmaxf(mrow1, m1);
        const float c0 = __expf(mrow0 - n0), c1 = __expf(mrow1 - n1);
        float ps0 = 0.f, ps1 = 0.f;
        float* P0 = Ps + (wm + qr) * AP_STR + 2 * qc;
        float* P1 = Ps + (wm + qr + 8) * AP_STR + 2 * qc;
        #pragma unroll
        for (int nt = 0; nt < 4; nt++) {
            const float p00 = __expf(s[nt][0] - n0);
            const float p01 = __expf(s[nt][1] - n0);
            const float p10 = __expf(s[nt][2] - n1);
            const float p11 = __expf(s[nt][3] - n1);
            ps0 += p00 + p01;
            ps1 += p10 + p11;
            P0[nt * 8 + 0] = __uint_as_float(f2tf(p00));
            P0[nt * 8 + 1] = __uint_as_float(f2tf(p01));
            P1[nt * 8 + 0] = __uint_as_float(f2tf(p10));
            P1[nt * 8 + 1] = __uint_as_float(f2tf(p11));
        }
        ps0 += __shfl_xor_sync(0xffffffffu, ps0, 1);
        ps0 += __shfl_xor_sync(0xffffffffu, ps0, 2);
        ps1 += __shfl_xor_sync(0xffffffffu, ps1, 1);
        ps1 += __shfl_xor_sync(0xffffffffu, ps1, 2);
        l0 = l0 * c0 + ps0;
        l1 = l1 * c1 + ps1;
        mrow0 = n0; mrow1 = n1;
        #pragma unroll
        for (int nt = 0; nt < 8; nt++) {
            o[nt][0] *= c0; o[nt][1] *= c0;
            o[nt][2] *= c1; o[nt][3] *= c1;
        }
        __syncwarp();                          // P visible within warp

        // O += P V  (k = 32 keys, n = 64 hd); V already tf32 -> raw loads
        #pragma unroll
        for (int ks2 = 0; ks2 < 4; ks2++) {
            uint32_t pa[4];
            pa[0] = __float_as_uint(Ps[(wm + qr) * AP_STR + ks2 * 8 + qc]);
            pa[1] = __float_as_uint(Ps[(wm + qr + 8) * AP_STR + ks2 * 8 + qc]);
            pa[2] = __float_as_uint(Ps[(wm + qr) * AP_STR + ks2 * 8 + qc + 4]);
            pa[3] = __float_as_uint(Ps[(wm + qr + 8) * AP_STR + ks2 * 8 + qc + 4]);
            #pragma unroll
            for (int nt = 0; nt < 8; nt++) {
                uint32_t bv[2];
                bv[0] = __float_as_uint(Vc[(ks2 * 8 + qc) * AV_STR + nt * 8 + qr]);
                bv[1] = __float_as_uint(Vc[(ks2 * 8 + qc + 4) * AV_STR + nt * 8 + qr]);
                MMA_TF32(o[nt], pa, bv);
            }
        }
        __syncwarp();                          // P reads done before next write
    }

    const float i0 = 1.0f / l0, i1 = 1.0f / l1;
    const long r0g = (long)(b * SS + q0 + wm + qr);
    float* d0 = out + r0g * EE + h * 64 + 2 * qc;
    float* d1 = d0 + 8 * EE;
    #pragma unroll
    for (int nt = 0; nt < 8; nt++) {
        float2 v0, v1;
        v0.x = tf32r(o[nt][0] * i0); v0.y = tf32r(o[nt][1] * i0);
        v1.x = tf32r(o[nt][2] * i1); v1.y = tf32r(o[nt][3] * i1);
        *(float2*)(d0 + nt * 8) = v0;
        *(float2*)(d1 + nt * 8) = v1;
    }
}

// ---------------------------------------------------------------------------
// Launch sequence
// ---------------------------------------------------------------------------
extern "C" void kernel_launch(void* const* d_in, const int* in_sizes, int n_in,
                              void* d_out, int out_size)
{
    const float* x         = (const float*)d_in[0];
    const float* ln1_w     = (const float*)d_in[1];
    const float* ln1_b     = (const float*)d_in[2];
    const float* ln2_w     = (const float*)d_in[3];
    const float* ln2_b     = (const float*)d_in[4];
    const float* in_proj_w = (const float*)d_in[5];
    const float* in_proj_b = (const float*)d_in[6];
    const float* out_w     = (const float*)d_in[7];
    const float* out_b     = (const float*)d_in[8];
    const float* w1        = (const float*)d_in[9];
    const float* b1        = (const float*)d_in[10];
    const float* w2        = (const float*)d_in[11];
    const float* b2        = (const float*)d_in[12];
    float* outp            = (float*)d_out;

    float *h, *qkv, *attn, *x2, *ffn, *wq, *wo, *w1t, *w2t;
    cudaGetSymbolAddress((void**)&h,    g_h);
    cudaGetSymbolAddress((void**)&qkv,  g_qkv);
    cudaGetSymbolAddress((void**)&attn, g_attn);
    cudaGetSymbolAddress((void**)&x2,   g_x2);
    cudaGetSymbolAddress((void**)&ffn,  g_ffn);
    cudaGetSymbolAddress((void**)&wq,   g_wq);
    cudaGetSymbolAddress((void**)&wo,   g_wo);
    cudaGetSymbolAddress((void**)&w1t,  g_w1);
    cudaGetSymbolAddress((void**)&w2t,  g_w2);

    cudaFuncSetAttribute(gemm_mma<EPI_NONE, true>,  cudaFuncAttributeMaxDynamicSharedMemorySize, DSMEM_SZ);
    cudaFuncSetAttribute(gemm_mma<EPI_GELU, true>,  cudaFuncAttributeMaxDynamicSharedMemorySize, DSMEM_SZ);
    cudaFuncSetAttribute(gemm_mma<EPI_RES,  false>, cudaFuncAttributeMaxDynamicSharedMemorySize, DSMEM_SZ);
    cudaFuncSetAttribute(attn_mma, cudaFuncAttributeMaxDynamicSharedMemorySize, ATTN_SMEM);

    // 0. pre-round weights to tf32 (HBM-bound, ~30us total)
    tf32_cast<<<(3 * EE * EE / 4 + 255) / 256, 256>>>(in_proj_w, wq, 3 * EE * EE / 4);
    tf32_cast<<<(EE * EE / 4 + 255) / 256, 256>>>(out_w, wo, EE * EE / 4);
    tf32_cast<<<(FFN * EE / 4 + 255) / 256, 256>>>(w1, w1t, FFN * EE / 4);
    tf32_cast<<<(EE * FFN / 4 + 255) / 256, 256>>>(w2, w2t, EE * FFN / 4);

    // 1. h = tf32(LN1(x))
    ln_kernel<<<MM, 256>>>(x, ln1_w, ln1_b, h);
    // 2. qkv = tf32(h @ wq^T + b)                     [16384, 3072]
    gemm_mma<EPI_NONE, true><<<dim3(3 * EE / 128, MM / 128), 256, DSMEM_SZ>>>(
        h, wq, in_proj_b, nullptr, qkv, 3 * EE, EE);
    // 3. attention (tf32 in, tf32-rounded out)
    attn_mma<<<dim3(SS / 64, BB * HH), 128, ATTN_SMEM>>>(qkv, attn);
    // 4. x2 = x + attn @ wo^T + out_b                 (full fp32)
    gemm_mma<EPI_RES, false><<<dim3(EE / 128, MM / 128), 256, DSMEM_SZ>>>(
        attn, wo, out_b, x, x2, EE, EE);
    // 5. h = tf32(LN2(x2))
    ln_kernel<<<MM, 256>>>(x2, ln2_w, ln2_b, h);
    // 6. ffn = tf32(gelu(h @ w1^T + b1))              [16384, 4096]
    gemm_mma<EPI_GELU, true><<<dim3(FFN / 128, MM / 128), 256, DSMEM_SZ>>>(
        h, w1t, b1, nullptr, ffn, FFN, EE);
    // 7. out = x2 + ffn @ w2^T + b2                   (full fp32)
    gemm_mma<EPI_RES, false><<<dim3(EE / 128, MM / 128), 256, DSMEM_SZ>>>(
        ffn, w2t, b2, x2, outp, EE, FFN);
}

// round 13
// speedup vs baseline: 4.3724x; 1.0089x over previous
#include <cuda_runtime.h>
#include <cuda_bf16.h>
#include <math.h>
#include <stdint.h>

// ---------------------------------------------------------------------------
// Problem constants
// ---------------------------------------------------------------------------
#define BB   16
#define SS   1024
#define EE   1024
#define HH   16
#define HD   64
#define FFN  4096
#define MM   (BB * SS)          // 16384 rows

// ---------------------------------------------------------------------------
// Scratch buffers (device globals: allocation-free, graph-capture safe)
// ---------------------------------------------------------------------------
__device__ float g_h   [(size_t)MM * EE];
__device__ float g_qkv [(size_t)MM * 3 * EE];
__device__ float g_attn[(size_t)MM * EE];
__device__ float g_x2  [(size_t)MM * EE];
__device__ float g_ffn [(size_t)MM * FFN];
// pre-rounded tf32 weights
__device__ float g_wq  [(size_t)3 * EE * EE];
__device__ float g_wo  [(size_t)EE * EE];
__device__ float g_w1  [(size_t)FFN * EE];
__device__ float g_w2  [(size_t)EE * FFN];

// ---------------------------------------------------------------------------
// PTX helpers (sm_100 plain target: cp.async + mma.sync + ldmatrix)
// ---------------------------------------------------------------------------
__device__ __forceinline__ uint32_t smem_u32(const void* p) {
    uint32_t a;
    asm("{ .reg .u64 t; cvta.to.shared.u64 t, %1; cvt.u32.u64 %0, t; }"
        : "=r"(a) : "l"(p));
    return a;
}

__device__ __forceinline__ void cp_async16(uint32_t dst, const void* src) {
    asm volatile("cp.async.cg.shared.global [%0], [%1], 16;"
                 :: "r"(dst), "l"(src) : "memory");
}
#define CP_COMMIT() asm volatile("cp.async.commit_group;" ::: "memory")
#define CP_WAIT(n)  asm volatile("cp.async.wait_group %0;" :: "n"(n) : "memory")

// round-to-nearest fp32 -> tf32 (producers only; hot loops load raw bits)
__device__ __forceinline__ uint32_t f2tf(float x) {
    uint32_t r;
    asm("cvt.rna.tf32.f32 %0, %1;" : "=r"(r) : "f"(x));
    return r;
}
__device__ __forceinline__ float tf32r(float x) {
    return __uint_as_float(f2tf(x));
}

#define MMA_TF32(c, a, b) \
    asm volatile("mma.sync.aligned.m16n8k8.row.col.f32.tf32.tf32.f32 " \
        "{%0,%1,%2,%3}, {%4,%5,%6,%7}, {%8,%9}, {%0,%1,%2,%3};" \
        : "+f"((c)[0]), "+f"((c)[1]), "+f"((c)[2]), "+f"((c)[3]) \
        : "r"((a)[0]), "r"((a)[1]), "r"((a)[2]), "r"((a)[3]), \
          "r"((b)[0]), "r"((b)[1]))

// ldmatrix: 8x8 b16 matrices; for tf32 an 8row x 8tf32col block = 2 matrices.
// x4 yields exactly the m16n8k8 A fragment {a0,a1,a2,a3}; x2 the B fragment.
#define LDSM_X4(r, addr) \
    asm volatile("ldmatrix.sync.aligned.m8n8.x4.shared.b16 {%0,%1,%2,%3}, [%4];" \
        : "=r"((r)[0]), "=r"((r)[1]), "=r"((r)[2]), "=r"((r)[3]) : "r"(addr))
#define LDSM_X2(r, addr) \
    asm volatile("ldmatrix.sync.aligned.m8n8.x2.shared.b16 {%0,%1}, [%2];" \
        : "=r"((r)[0]), "=r"((r)[1]) : "r"(addr))

// ---------------------------------------------------------------------------
// Weight pre-rounding: dst[i] = tf32(src[i]), vectorized
// ---------------------------------------------------------------------------
__global__ __launch_bounds__(256)
void tf32_cast(const float* __restrict__ s, float* __restrict__ d, int n4)
{
    const int i = blockIdx.x * 256 + threadIdx.x;
    if (i < n4) {
        float4 v = ((const float4*)s)[i];
        v.x = tf32r(v.x); v.y = tf32r(v.y);
        v.z = tf32r(v.z); v.w = tf32r(v.w);
        ((float4*)d)[i] = v;
    }
}

// ---------------------------------------------------------------------------
// tf32 mma.sync GEMM: C[M,N] = A[M,K] @ W[N,K]^T + bias (+gelu / +residual)
//   Single __syncthreads per k-iter: wait(1) -> sync -> prefetch -> compute.
//   128x128 CTA tile, BK=32, 8 warps (2x4), warp tile 64x32, ldmatrix frags,
//   3-stage cp.async pipeline, XOR-swizzled smem (32KB/stage -> 2 CTA/SM).
// ---------------------------------------------------------------------------
#define EPI_NONE 0
#define EPI_GELU 1
#define EPI_RES  2

#define GBK       32
#define GSTAGES   3
#define STAGE_FLT (2 * 128 * 32)              // A block then B block (floats)
#define STAGE_B   (STAGE_FLT * 4)
#define ABLK_B    (128 * 32 * 4)              // 16384 bytes
#define DSMEM_SZ  (GSTAGES * STAGE_B)         // 98304 bytes

template<int EPI, bool RND>
__global__ __launch_bounds__(256, 2)
void gemm_mma(const float* __restrict__ A, const float* __restrict__ W,
              const float* __restrict__ bias, const float* __restrict__ Res,
              float* __restrict__ C, int N, int K)
{
    extern __shared__ float sm[];
    const uint32_t smA = smem_u32(sm);

    const int tid  = threadIdx.x;
    const int bm   = blockIdx.y * 128;
    const int bn   = blockIdx.x * 128;
    const int warp = tid >> 5, lane = tid & 31;
    const int wm   = (warp >> 2) * 64;        // 0,64
    const int wn   = (warp & 3) * 32;         // 0,32,64,96
    const int qr   = lane >> 2;               // 0..7
    const int qc   = lane & 3;                // 0..3
    const int lx   = lane & 7;

    // per-lane ldmatrix row bases (bytes, stage-relative)
    const uint32_t aRow = (uint32_t)(wm + (lane & 15)) << 7;          // row*128B
    const uint32_t aBit = (uint32_t)(lane >> 4);                      // col-half
    const uint32_t bRow = (uint32_t)(wn + lx) << 7;
    const uint32_t bBit = (uint32_t)((lane >> 3) & 1);

    float acc[4][4][4];
    #pragma unroll
    for (int i = 0; i < 4; i++)
        #pragma unroll
        for (int j = 0; j < 4; j++)
            #pragma unroll
            for (int k = 0; k < 4; k++) acc[i][j][k] = 0.f;

    // cp.async mapping: thread -> row tid>>1, chunk base (tid&1)*4, 4 x 16B
    const int  lrow = tid >> 1;
    const int  cb   = (tid & 1) * 4;
    const float* Ap = A + (long)(bm + lrow) * K;
    const float* Wp = W + (long)(bn + lrow) * K;
    const uint32_t dA = smA + lrow * 128;
    const uint32_t dB = smA + ABLK_B + lrow * 128;
    const int rx = lrow & 7;

    const int T = K / GBK;

    // prologue: stages 0,1 (2 committed groups)
    #pragma unroll
    for (int u = 0; u < 2; ++u) {
        const uint32_t sb = u * STAGE_B;
        #pragma unroll
        for (int j = 0; j < 4; j++) {
            const int c = cb + j;
            const uint32_t so = ((c ^ rx) << 4);
            cp_async16(dA + sb + so, Ap + (long)u * GBK + c * 4);
            cp_async16(dB + sb + so, Wp + (long)u * GBK + c * 4);
        }
        CP_COMMIT();
    }

    for (int t = 0; t < T; ++t) {
        // invariant: before wait, committed groups g0..g_{t+1}; wait(1) => g_t done
        CP_WAIT(1);
        __syncthreads();                      // all warps done reading stage (t-1)%3

        if (t + 2 < T) {                      // prefetch into stage (t+2)%3 = (t-1)%3
            const int u = t + 2;
            const uint32_t sb = (u % GSTAGES) * STAGE_B;
            #pragma unroll
            for (int j = 0; j < 4; j++) {
                const int c = cb + j;
                const uint32_t so = ((c ^ rx) << 4);
                cp_async16(dA + sb + so, Ap + (long)u * GBK + c * 4);
                cp_async16(dB + sb + so, Wp + (long)u * GBK + c * 4);
            }
        }
        CP_COMMIT();                          // unconditional: keeps group accounting

        const uint32_t stb = smA + (t % GSTAGES) * STAGE_B;

        #pragma unroll
        for (int ks = 0; ks < 4; ++ks) {
            uint32_t a[4][4], b[4][2];
            const uint32_t aAddr = stb + aRow
                                 + ((((uint32_t)(ks << 1) + aBit) ^ (aRow >> 7 & 7u)) << 4);
            const uint32_t bAddr = stb + ABLK_B + bRow
                                 + ((((uint32_t)(ks << 1) + bBit) ^ lx) << 4);
            #pragma unroll
            for (int mt = 0; mt < 4; ++mt)
                LDSM_X4(a[mt], aAddr + mt * 2048);
            #pragma unroll
            for (int nt = 0; nt < 4; ++nt)
                LDSM_X2(b[nt], bAddr + nt * 1024);
            #pragma unroll
            for (int mt = 0; mt < 4; ++mt)
                #pragma unroll
                for (int nt = 0; nt < 4; ++nt)
                    MMA_TF32(acc[mt][nt], a[mt], b[nt]);
        }
    }

    // epilogue (regs only; no smem reuse -> no sync needed)
    #pragma unroll
    for (int mt = 0; mt < 4; ++mt) {
        #pragma unroll
        for (int r2 = 0; r2 < 2; ++r2) {
            const long row = bm + wm + mt * 16 + qr + r2 * 8;
            float* Crow = C + row * (long)N + bn;
            const float* Rrow = (EPI == EPI_RES) ? (Res + row * (long)N + bn)
                                                 : (const float*)nullptr;
            #pragma unroll
            for (int nt = 0; nt < 4; ++nt) {
                const int col = wn + nt * 8 + qc * 2;
                float2 v;
                v.x = acc[mt][nt][r2 * 2 + 0];
                v.y = acc[mt][nt][r2 * 2 + 1];
                const float2 bv = *(const float2*)(bias + bn + col);
                v.x += bv.x; v.y += bv.y;
                if (EPI == EPI_GELU) {
                    v.x = 0.5f * v.x * (1.0f + erff(v.x * 0.7071067811865475f));
                    v.y = 0.5f * v.y * (1.0f + erff(v.y * 0.7071067811865475f));
                }
                if (EPI == EPI_RES) {
                    const float2 rv = *(const float2*)(Rrow + col);
                    v.x += rv.x; v.y += rv.y;
                }
                if (RND) { v.x = tf32r(v.x); v.y = tf32r(v.y); }
                *(float2*)(Crow + col) = v;
            }
        }
    }
}

// ---------------------------------------------------------------------------
// LayerNorm: output rounded to tf32 (consumed only as GEMM A operand)
// ---------------------------------------------------------------------------
__global__ __launch_bounds__(256)
void ln_kernel(const float* __restrict__ x, const float* __restrict__ w,
               const float* __restrict__ b, float* __restrict__ y)
{
    const long row = blockIdx.x;
    const float4* xr = (const float4*)(x + (row << 10));
    float4 xv = xr[threadIdx.x];

    float s  = xv.x + xv.y + xv.z + xv.w;
    float sq = xv.x * xv.x + xv.y * xv.y + xv.z * xv.z + xv.w * xv.w;
    #pragma unroll
    for (int o = 16; o; o >>= 1) {
        s  += __shfl_xor_sync(0xffffffffu, s,  o);
        sq += __shfl_xor_sync(0xffffffffu, sq, o);
    }
    __shared__ float ss[8], ssq[8];
    __shared__ float mu_s, rstd_s;
    const int warp = threadIdx.x >> 5, lane = threadIdx.x & 31;
    if (lane == 0) { ss[warp] = s; ssq[warp] = sq; }
    __syncthreads();
    if (threadIdx.x == 0) {
        float S = 0.f, SQ = 0.f;
        #pragma unroll
        for (int i = 0; i < 8; i++) { S += ss[i]; SQ += ssq[i]; }
        const float mu  = S * (1.0f / 1024.0f);
        const float var = SQ * (1.0f / 1024.0f) - mu * mu;
        mu_s   = mu;
        rstd_s = rsqrtf(var + 1e-6f);
    }
    __syncthreads();
    const float mu = mu_s, rstd = rstd_s;

    const float4 wv = ((const float4*)w)[threadIdx.x];
    const float4 bv = ((const float4*)b)[threadIdx.x];
    float4 o;
    o.x = tf32r((xv.x - mu) * rstd * wv.x + bv.x);
    o.y = tf32r((xv.y - mu) * rstd * wv.y + bv.y);
    o.z = tf32r((xv.z - mu) * rstd * wv.z + bv.z);
    o.w = tf32r((xv.w - mu) * rstd * wv.w + bv.w);
    ((float4*)(y + (row << 10)))[threadIdx.x] = o;
}

// ---------------------------------------------------------------------------
// Flash attention, tf32 mma.sync, Q-tile 128 (256 threads, 8 warps):
//   halves K/V L2 traffic vs 64-row tiles. Single sync per key-tile:
//   wait(0) -> sync -> prefetch -> compute (double-buffered K/V).
// ---------------------------------------------------------------------------
#define AQ_STR 68
#define AK_STR 68
#define AV_STR 72
#define AP_STR 36
#define QROWS  128
#define AQ_FLT (QROWS * AQ_STR)           // 8704
#define AK_FLT (2 * 32 * AK_STR)          // 4352
#define AV_FLT (2 * 32 * AV_STR)          // 4608
#define AP_FLT (QROWS * AP_STR)           // 4608
#define ATTN_SMEM ((AQ_FLT + AK_FLT + AV_FLT + AP_FLT) * 4)  // 89088 B

__global__ __launch_bounds__(256, 2)
void attn_mma(const float* __restrict__ qkv, float* __restrict__ out)
{
    extern __shared__ float asmem[];
    float* Qs = asmem;
    float* Ks = Qs + AQ_FLT;
    float* Vs = Ks + AK_FLT;
    float* Ps = Vs + AV_FLT;

    const int tid  = threadIdx.x;
    const int warp = tid >> 5, lane = tid & 31;
    const int qr   = lane >> 2, qc = lane & 3;
    const int lx   = lane & 7;
    const int b    = blockIdx.y >> 4, h = blockIdx.y & 15;
    const int q0   = blockIdx.x * QROWS;
    const int wm   = warp * 16;               // 0..112
    const long base = (long)b * SS * 3072 + h * 64;

    const uint32_t sQ = smem_u32(Qs), sK = smem_u32(Ks), sV = smem_u32(Vs);

    // Q tile (128 rows x 16 chunks = 2048): 8 per thread
    #pragma unroll
    for (int i = 0; i < 8; i++) {
        const int cc = tid + i * 256;
        const int row = cc >> 4, c = cc & 15;
        cp_async16(sQ + (row * AQ_STR + c * 4) * 4,
                   qkv + base + (long)(q0 + row) * 3072 + c * 4);
    }
    // K/V tile kt=0 (512 chunks each): 2 per thread each
    #pragma unroll
    for (int i = 0; i < 2; i++) {
        const int cc = tid + i * 256;
        const int row = cc >> 4, c = cc & 15;
        const long ko = base + 1024 + (long)row * 3072 + c * 4;
        cp_async16(sK + (row * AK_STR + c * 4) * 4, qkv + ko);
        cp_async16(sV + (row * AV_STR + c * 4) * 4, qkv + ko + 1024);
    }
    CP_COMMIT();
    CP_WAIT(0);
    __syncthreads();

    // Q fragments: x0.125 is exact (power of 2) on already-tf32 values
    uint32_t qa[8][4];
    {
        const int r0 = wm + qr, r1 = r0 + 8;
        #pragma unroll
        for (int ks = 0; ks < 8; ks++) {
            qa[ks][0] = __float_as_uint(Qs[r0 * AQ_STR + ks * 8 + qc] * 0.125f);
            qa[ks][1] = __float_as_uint(Qs[r1 * AQ_STR + ks * 8 + qc] * 0.125f);
            qa[ks][2] = __float_as_uint(Qs[r0 * AQ_STR + ks * 8 + qc + 4] * 0.125f);
            qa[ks][3] = __float_as_uint(Qs[r1 * AQ_STR + ks * 8 + qc + 4] * 0.125f);
        }
    }

    // ldmatrix per-lane row/half for K (B-operand pattern)
    const uint32_t kRowOff = (uint32_t)lx * (AK_STR * 4);   // row*272B
    const uint32_t kBit    = (uint32_t)((lane >> 3) & 1);

    float o[8][4];
    #pragma unroll
    for (int nt = 0; nt < 8; nt++)
        #pragma unroll
        for (int k = 0; k < 4; k++) o[nt][k] = 0.f;
    float mrow0 = -1e30f, mrow1 = -1e30f, l0 = 0.f, l1 = 0.f;

    for (int kt = 0; kt < 32; kt++) {
        const int cur = kt & 1;
        CP_WAIT(0);                            // buffer cur ready
        __syncthreads();                       // all warps done with buf cur^1
        if (kt + 1 < 32) {                     // prefetch next into cur^1
            const int nxt = cur ^ 1;
            #pragma unroll
            for (int i = 0; i < 2; i++) {
                const int cc = tid + i * 256;
                const int row = cc >> 4, c = cc & 15;
                const long ko = base + 1024
                              + (long)((kt + 1) * 32 + row) * 3072 + c * 4;
                cp_async16(sK + ((nxt * 32 + row) * AK_STR + c * 4) * 4, qkv + ko);
                cp_async16(sV + ((nxt * 32 + row) * AV_STR + c * 4) * 4, qkv + ko + 1024);
            }
        }
        CP_COMMIT();

        const uint32_t sKc = sK + cur * 32 * AK_STR * 4;
        const float*   Vc  = Vs + cur * 32 * AV_STR;

        // S = (Q/8) K^T  (warp tile 16 x 32 keys), K frags via ldmatrix.x2
        float s[4][4];
        #pragma unroll
        for (int nt = 0; nt < 4; nt++)
            #pragma unroll
            for (int k = 0; k < 4; k++) s[nt][k] = 0.f;
        #pragma unroll
        for (int ks = 0; ks < 8; ks++) {
            const uint32_t kAddr = sKc + kRowOff + (((uint32_t)(ks << 1) + kBit) << 4);
            uint32_t bf[4][2];
            #pragma unroll
            for (int nt = 0; nt < 4; nt++)
                LDSM_X2(bf[nt], kAddr + nt * (8 * AK_STR * 4));
            #pragma unroll
            for (int nt = 0; nt < 4; nt++)
                MMA_TF32(s[nt], qa[ks], bf[nt]);
        }

        // online softmax (rows r0 = wm+qr, r1 = wm+qr+8; quad owns each row)
        float m0 = -1e30f, m1 = -1e30f;
        #pragma unroll
        for (int nt = 0; nt < 4; nt++) {
            m0 = fmaxf(m0, fmaxf(s[nt][0], s[nt][1]));
            m1 = fmaxf(m1, fmaxf(s[nt][2], s[nt][3]));
        }
        m0 = fmaxf(m0, __shfl_xor_sync(0xffffffffu, m0, 1));
        m0 = fmaxf(m0, __shfl_xor_sync(0xffffffffu, m0, 2));
        m1 = fmaxf(m1, __shfl_xor_sync(0xffffffffu, m1, 1));
        m1 = fmaxf(m1, __shfl_xor_sync(0xffffffffu, m1, 2));
        const float n0 = fmaxf(mrow0, m0), n1 = fmaxf(mrow1, m1);
        const float c0 = __expf(mrow0 - n0), c1 = __expf(mrow1 - n1);
        float ps0 = 0.f, ps1 = 0.f;
        float* P0 = Ps + (wm + qr) * AP_STR + 2 * qc;
        float* P1 = Ps + (wm + qr + 8) * AP_STR + 2 * qc;
        #pragma unroll
        for (int nt = 0; nt < 4; nt++) {
            const float p00 = __expf(s[nt][0] - n0);
            const float p01 = __expf(s[nt][1] - n0);
            const float p10 = __expf(s[nt][2] - n1);
            const float p11 = __expf(s[nt][3] - n1);
            ps0 += p00 + p01;
            ps1 += p10 + p11;
            P0[nt * 8 + 0] = __uint_as_float(f2tf(p00));
            P0[nt * 8 + 1] = __uint_as_float(f2tf(p01));
            P1[nt * 8 + 0] = __uint_as_float(f2tf(p10));
            P1[nt * 8 + 1] = __uint_as_float(f2tf(p11));
        }
        ps0 += __shfl_xor_sync(0xffffffffu, ps0, 1);
        ps0 += __shfl_xor_sync(0xffffffffu, ps0, 2);
        ps1 += __shfl_xor_sync(0xffffffffu, ps1, 1);
        ps1 += __shfl_xor_sync(0xffffffffu, ps1, 2);
        l0 = l0 * c0 + ps0;
        l1 = l1 * c1 + ps1;
        mrow0 = n0; mrow1 = n1;
        #pragma unroll
        for (int nt = 0; nt < 8; nt++) {
            o[nt][0] *= c0; o[nt][1] *= c0;
            o[nt][2] *= c1; o[nt][3] *= c1;
        }
        __syncwarp();                          // P visible within warp

        // O += P V  (k = 32 keys, n = 64 hd); V already tf32 -> raw loads
        #pragma unroll
        for (int ks2 = 0; ks2 < 4; ks2++) {
            uint32_t pa[4];
            pa[0] = __float_as_uint(Ps[(wm + qr) * AP_STR + ks2 * 8 + qc]);
            pa[1] = __float_as_uint(Ps[(wm + qr + 8) * AP_STR + ks2 * 8 + qc]);
            pa[2] = __float_as_uint(Ps[(wm + qr) * AP_STR + ks2 * 8 + qc + 4]);
            pa[3] = __float_as_uint(Ps[(wm + qr + 8) * AP_STR + ks2 * 8 + qc + 4]);
            #pragma unroll
            for (int nt = 0; nt < 8; nt++) {
                uint32_t bv[2];
                bv[0] = __float_as_uint(Vc[(ks2 * 8 + qc) * AV_STR + nt * 8 + qr]);
                bv[1] = __float_as_uint(Vc[(ks2 * 8 + qc + 4) * AV_STR + nt * 8 + qr]);
                MMA_TF32(o[nt], pa, bv);
            }
        }
        __syncwarp();                          // P reads done before next write
    }

    const float i0 = 1.0f / l0, i1 = 1.0f / l1;
    const long r0g = (long)(b * SS + q0 + wm + qr);
    float* d0 = out + r0g * EE + h * 64 + 2 * qc;
    float* d1 = d0 + 8 * EE;
    #pragma unroll
    for (int nt = 0; nt < 8; nt++) {
        float2 v0, v1;
        v0.x = tf32r(o[nt][0] * i0); v0.y = tf32r(o[nt][1] * i0);
        v1.x = tf32r(o[nt][2] * i1); v1.y = tf32r(o[nt][3] * i1);
        *(float2*)(d0 + nt * 8) = v0;
        *(float2*)(d1 + nt * 8) = v1;
    }
}

// ---------------------------------------------------------------------------
// Launch sequence
// ---------------------------------------------------------------------------
extern "C" void kernel_launch(void* const* d_in, const int* in_sizes, int n_in,
                              void* d_out, int out_size)
{
    const float* x         = (const float*)d_in[0];
    const float* ln1_w     = (const float*)d_in[1];
    const float* ln1_b     = (const float*)d_in[2];
    const float* ln2_w     = (const float*)d_in[3];
    const float* ln2_b     = (const float*)d_in[4];
    const float* in_proj_w = (const float*)d_in[5];
    const float* in_proj_b = (const float*)d_in[6];
    const float* out_w     = (const float*)d_in[7];
    const float* out_b     = (const float*)d_in[8];
    const float* w1        = (const float*)d_in[9];
    const float* b1        = (const float*)d_in[10];
    const float* w2        = (const float*)d_in[11];
    const float* b2        = (const float*)d_in[12];
    float* outp            = (float*)d_out;

    float *h, *qkv, *attn, *x2, *ffn, *wq, *wo, *w1t, *w2t;
    cudaGetSymbolAddress((void**)&h,    g_h);
    cudaGetSymbolAddress((void**)&qkv,  g_qkv);
    cudaGetSymbolAddress((void**)&attn, g_attn);
    cudaGetSymbolAddress((void**)&x2,   g_x2);
    cudaGetSymbolAddress((void**)&ffn,  g_ffn);
    cudaGetSymbolAddress((void**)&wq,   g_wq);
    cudaGetSymbolAddress((void**)&wo,   g_wo);
    cudaGetSymbolAddress((void**)&w1t,  g_w1);
    cudaGetSymbolAddress((void**)&w2t,  g_w2);

    cudaFuncSetAttribute(gemm_mma<EPI_NONE, true>,  cudaFuncAttributeMaxDynamicSharedMemorySize, DSMEM_SZ);
    cudaFuncSetAttribute(gemm_mma<EPI_GELU, true>,  cudaFuncAttributeMaxDynamicSharedMemorySize, DSMEM_SZ);
    cudaFuncSetAttribute(gemm_mma<EPI_RES,  false>, cudaFuncAttributeMaxDynamicSharedMemorySize, DSMEM_SZ);
    cudaFuncSetAttribute(attn_mma, cudaFuncAttributeMaxDynamicSharedMemorySize, ATTN_SMEM);

    // 0. pre-round weights to tf32 (HBM-bound, ~30us total)
    tf32_cast<<<(3 * EE * EE / 4 + 255) / 256, 256>>>(in_proj_w, wq, 3 * EE * EE / 4);
    tf32_cast<<<(EE * EE / 4 + 255) / 256, 256>>>(out_w, wo, EE * EE / 4);
    tf32_cast<<<(FFN * EE / 4 + 255) / 256, 256>>>(w1, w1t, FFN * EE / 4);
    tf32_cast<<<(EE * FFN / 4 + 255) / 256, 256>>>(w2, w2t, EE * FFN / 4);

    // 1. h = tf32(LN1(x))
    ln_kernel<<<MM, 256>>>(x, ln1_w, ln1_b, h);
    // 2. qkv = tf32(h @ wq^T + b)                     [16384, 3072]
    gemm_mma<EPI_NONE, true><<<dim3(3 * EE / 128, MM / 128), 256, DSMEM_SZ>>>(
        h, wq, in_proj_b, nullptr, qkv, 3 * EE, EE);
    // 3. attention (tf32 in, tf32-rounded out), Q-tile 128
    attn_mma<<<dim3(SS / QROWS, BB * HH), 256, ATTN_SMEM>>>(qkv, attn);
    // 4. x2 = x + attn @ wo^T + out_b                 (full fp32)
    gemm_mma<EPI_RES, false><<<dim3(EE / 128, MM / 128), 256, DSMEM_SZ>>>(
        attn, wo, out_b, x, x2, EE, EE);
    // 5. h = tf32(LN2(x2))
    ln_kernel<<<MM, 256>>>(x2, ln2_w, ln2_b, h);
    // 6. ffn = tf32(gelu(h @ w1^T + b1))              [16384, 4096]
    gemm_mma<EPI_GELU, true><<<dim3(FFN / 128, MM / 128), 256, DSMEM_SZ>>>(
        h, w1t, b1, nullptr, ffn, FFN, EE);
    // 7. out = x2 + ffn @ w2^T + b2                   (full fp32)
    gemm_mma<EPI_RES, false><<<dim3(EE / 128, MM / 128), 256, DSMEM_SZ>>>(
        ffn, w2t, b2, x2, outp, EE, FFN);
}

// round 15
// speedup vs baseline: 8.0733x; 1.8464x over previous
#include <cuda_runtime.h>
#include <cuda_fp16.h>
#include <math.h>
#include <stdint.h>

// ---------------------------------------------------------------------------
// Problem constants
// ---------------------------------------------------------------------------
#define BB   16
#define SS   1024
#define EE   1024
#define HH   16
#define HD   64
#define FFN  4096
#define MM   (BB * SS)          // 16384 rows

// ---------------------------------------------------------------------------
// Scratch buffers (device globals: allocation-free, graph-capture safe)
// ---------------------------------------------------------------------------
__device__ __align__(16) __half g_h   [(size_t)MM * EE];
__device__ __align__(16) __half g_qkv [(size_t)MM * 3 * EE];
__device__ __align__(16) __half g_attn[(size_t)MM * EE];
__device__ __align__(16) float  g_x2  [(size_t)MM * EE];
__device__ __align__(16) __half g_ffn [(size_t)MM * FFN];
// pre-cast fp16 weights
__device__ __align__(16) __half g_wq  [(size_t)3 * EE * EE];
__device__ __align__(16) __half g_wo  [(size_t)EE * EE];
__device__ __align__(16) __half g_w1  [(size_t)FFN * EE];
__device__ __align__(16) __half g_w2  [(size_t)EE * FFN];

// ---------------------------------------------------------------------------
// PTX helpers (sm_100 plain target: cp.async + mma.sync + ldmatrix)
// ---------------------------------------------------------------------------
__device__ __forceinline__ uint32_t smem_u32(const void* p) {
    uint32_t a;
    asm("{ .reg .u64 t; cvta.to.shared.u64 t, %1; cvt.u32.u64 %0, t; }"
        : "=r"(a) : "l"(p));
    return a;
}

__device__ __forceinline__ void cp_async16(uint32_t dst, const void* src) {
    asm volatile("cp.async.cg.shared.global [%0], [%1], 16;"
                 :: "r"(dst), "l"(src) : "memory");
}
#define CP_COMMIT() asm volatile("cp.async.commit_group;" ::: "memory")
#define CP_WAIT(n)  asm volatile("cp.async.wait_group %0;" :: "n"(n) : "memory")

// fp16 m16n8k16 mma, fp32 accumulate
#define MMA_F16(c, a, b) \
    asm volatile("mma.sync.aligned.m16n8k16.row.col.f32.f16.f16.f32 " \
        "{%0,%1,%2,%3}, {%4,%5,%6,%7}, {%8,%9}, {%0,%1,%2,%3};" \
        : "+f"((c)[0]), "+f"((c)[1]), "+f"((c)[2]), "+f"((c)[3]) \
        : "r"((a)[0]), "r"((a)[1]), "r"((a)[2]), "r"((a)[3]), \
          "r"((b)[0]), "r"((b)[1]))

#define LDSM_X4(r, addr) \
    asm volatile("ldmatrix.sync.aligned.m8n8.x4.shared.b16 {%0,%1,%2,%3}, [%4];" \
        : "=r"((r)[0]), "=r"((r)[1]), "=r"((r)[2]), "=r"((r)[3]) : "r"(addr))
#define LDSM_X2(r, addr) \
    asm volatile("ldmatrix.sync.aligned.m8n8.x2.shared.b16 {%0,%1}, [%2];" \
        : "=r"((r)[0]), "=r"((r)[1]) : "r"(addr))
#define LDSM_X2T(r, addr) \
    asm volatile("ldmatrix.sync.aligned.m8n8.x2.trans.shared.b16 {%0,%1}, [%2];" \
        : "=r"((r)[0]), "=r"((r)[1]) : "r"(addr))

__device__ __forceinline__ uint32_t pack_h2(float lo, float hi) {
    __half2 h = __floats2half2_rn(lo, hi);
    return *(uint32_t*)&h;
}

// ---------------------------------------------------------------------------
// Weight pre-cast: fp32 -> fp16
// ---------------------------------------------------------------------------
__global__ __launch_bounds__(256)
void half_cast(const float* __restrict__ s, __half* __restrict__ d, int n4)
{
    const int i = blockIdx.x * 256 + threadIdx.x;
    if (i < n4) {
        const float4 v = ((const float4*)s)[i];
        uint2 o;
        o.x = pack_h2(v.x, v.y);
        o.y = pack_h2(v.z, v.w);
        ((uint2*)d)[i] = o;
    }
}

// ---------------------------------------------------------------------------
// fp16 mma.sync GEMM: C[M,N] = A[M,K] @ W[N,K]^T + bias (+gelu / +residual)
//   A, W fp16; acc fp32. 128x128 CTA tile, BK=64 (rows = 128B = 8x16B chunks,
//   verified XOR swizzle), 8 warps (2x4), warp tile 64x32,
//   3-stage cp.async, single sync per k-iter, ldmatrix fragments.
// ---------------------------------------------------------------------------
#define EPI_NONE 0
#define EPI_GELU 1
#define EPI_RES  2

#define GBK       64
#define GSTAGES   3
#define ABLK_B    (128 * 128)                 // 16384 bytes (128 rows x 128B)
#define STAGE_B   (2 * ABLK_B)                // 32768
#define DSMEM_SZ  (GSTAGES * STAGE_B)         // 98304 bytes

template<int EPI, bool OH>
__global__ __launch_bounds__(256, 2)
void gemm_mma(const __half* __restrict__ A, const __half* __restrict__ W,
              const float* __restrict__ bias, const float* __restrict__ Res,
              void* __restrict__ Cv, int N, int K)
{
    extern __shared__ char smc[];
    const uint32_t smA = smem_u32(smc);

    const int tid  = threadIdx.x;
    const int bm   = blockIdx.y * 128;
    const int bn   = blockIdx.x * 128;
    const int warp = tid >> 5, lane = tid & 31;
    const int wm   = (warp >> 2) * 64;        // 0,64
    const int wn   = (warp & 3) * 32;         // 0,32,64,96
    const int qr   = lane >> 2;               // 0..7
    const int qc   = lane & 3;                // 0..3
    const int lx   = lane & 7;

    // per-lane ldmatrix row bases (bytes, stage-relative); rows are 128B
    const uint32_t aRow = (uint32_t)(wm + (lane & 15)) << 7;
    const uint32_t aBit = (uint32_t)(lane >> 4);
    const uint32_t bRow = (uint32_t)(wn + lx) << 7;
    const uint32_t bBit = (uint32_t)((lane >> 3) & 1);

    float acc[4][4][4];
    #pragma unroll
    for (int i = 0; i < 4; i++)
        #pragma unroll
        for (int j = 0; j < 4; j++)
            #pragma unroll
            for (int k = 0; k < 4; k++) acc[i][j][k] = 0.f;

    // cp.async: thread -> row tid>>1, chunk base (tid&1)*4, 4 x 16B (=8 fp16)
    const int  lrow = tid >> 1;
    const int  cb   = (tid & 1) * 4;
    const __half* Ap = A + (long)(bm + lrow) * K;
    const __half* Wp = W + (long)(bn + lrow) * K;
    const uint32_t dA = smA + lrow * 128;
    const uint32_t dB = smA + ABLK_B + lrow * 128;
    const int rx = lrow & 7;

    const int T = K / GBK;

    // prologue: stages 0,1
    #pragma unroll
    for (int u = 0; u < 2; ++u) {
        const uint32_t sb = u * STAGE_B;
        #pragma unroll
        for (int j = 0; j < 4; j++) {
            const int c = cb + j;
            const uint32_t so = ((c ^ rx) << 4);
            cp_async16(dA + sb + so, Ap + (long)u * GBK + c * 8);
            cp_async16(dB + sb + so, Wp + (long)u * GBK + c * 8);
        }
        CP_COMMIT();
    }

    for (int t = 0; t < T; ++t) {
        CP_WAIT(1);
        __syncthreads();                      // all warps done reading stage (t-1)%3

        if (t + 2 < T) {
            const int u = t + 2;
            const uint32_t sb = (u % GSTAGES) * STAGE_B;
            #pragma unroll
            for (int j = 0; j < 4; j++) {
                const int c = cb + j;
                const uint32_t so = ((c ^ rx) << 4);
                cp_async16(dA + sb + so, Ap + (long)u * GBK + c * 8);
                cp_async16(dB + sb + so, Wp + (long)u * GBK + c * 8);
            }
        }
        CP_COMMIT();

        const uint32_t stb = smA + (t % GSTAGES) * STAGE_B;

        #pragma unroll
        for (int ks = 0; ks < 4; ++ks) {      // 4 x k16 = 64 K per iter
            uint32_t a[4][4], b[4][2];
            const uint32_t aAddr = stb + aRow
                                 + ((((uint32_t)(ks << 1) + aBit) ^ ((aRow >> 7) & 7u)) << 4);
            const uint32_t bAddr = stb + ABLK_B + bRow
                                 + ((((uint32_t)(ks << 1) + bBit) ^ (uint32_t)lx) << 4);
            #pragma unroll
            for (int mt = 0; mt < 4; ++mt)
                LDSM_X4(a[mt], aAddr + mt * 2048);
            #pragma unroll
            for (int nt = 0; nt < 4; ++nt)
                LDSM_X2(b[nt], bAddr + nt * 1024);
            #pragma unroll
            for (int mt = 0; mt < 4; ++mt)
                #pragma unroll
                for (int nt = 0; nt < 4; ++nt)
                    MMA_F16(acc[mt][nt], a[mt], b[nt]);
        }
    }

    // epilogue (acc fp32; OH -> fp16 output, else fp32)
    #pragma unroll
    for (int mt = 0; mt < 4; ++mt) {
        #pragma unroll
        for (int r2 = 0; r2 < 2; ++r2) {
            const long row = bm + wm + mt * 16 + qr + r2 * 8;
            const float* Rrow = (EPI == EPI_RES) ? (Res + row * (long)N + bn)
                                                 : (const float*)nullptr;
            #pragma unroll
            for (int nt = 0; nt < 4; ++nt) {
                const int col = wn + nt * 8 + qc * 2;
                float vx = acc[mt][nt][r2 * 2 + 0];
                float vy = acc[mt][nt][r2 * 2 + 1];
                const float2 bv = *(const float2*)(bias + bn + col);
                vx += bv.x; vy += bv.y;
                if (EPI == EPI_GELU) {
                    vx = 0.5f * vx * (1.0f + erff(vx * 0.7071067811865475f));
                    vy = 0.5f * vy * (1.0f + erff(vy * 0.7071067811865475f));
                }
                if (EPI == EPI_RES) {
                    const float2 rv = *(const float2*)(Rrow + col);
                    vx += rv.x; vy += rv.y;
                }
                if (OH) {
                    __half* Crow = (__half*)Cv + row * (long)N + bn;
                    *(uint32_t*)(Crow + col) = pack_h2(vx, vy);
                } else {
                    float* Crow = (float*)Cv + row * (long)N + bn;
                    float2 o; o.x = vx; o.y = vy;
                    *(float2*)(Crow + col) = o;
                }
            }
        }
    }
}

// ---------------------------------------------------------------------------
// LayerNorm: fp32 in, fp16 out (consumed only as GEMM A operand)
// ---------------------------------------------------------------------------
__global__ __launch_bounds__(256)
void ln_kernel(const float* __restrict__ x, const float* __restrict__ w,
               const float* __restrict__ b, __half* __restrict__ y)
{
    const long row = blockIdx.x;
    const float4* xr = (const float4*)(x + (row << 10));
    float4 xv = xr[threadIdx.x];

    float s  = xv.x + xv.y + xv.z + xv.w;
    float sq = xv.x * xv.x + xv.y * xv.y + xv.z * xv.z + xv.w * xv.w;
    #pragma unroll
    for (int o = 16; o; o >>= 1) {
        s  += __shfl_xor_sync(0xffffffffu, s,  o);
        sq += __shfl_xor_sync(0xffffffffu, sq, o);
    }
    __shared__ float ss[8], ssq[8];
    __shared__ float mu_s, rstd_s;
    const int warp = threadIdx.x >> 5, lane = threadIdx.x & 31;
    if (lane == 0) { ss[warp] = s; ssq[warp] = sq; }
    __syncthreads();
    if (threadIdx.x == 0) {
        float S = 0.f, SQ = 0.f;
        #pragma unroll
        for (int i = 0; i < 8; i++) { S += ss[i]; SQ += ssq[i]; }
        const float mu  = S * (1.0f / 1024.0f);
        const float var = SQ * (1.0f / 1024.0f) - mu * mu;
        mu_s   = mu;
        rstd_s = rsqrtf(var + 1e-6f);
    }
    __syncthreads();
    const float mu = mu_s, rstd = rstd_s;

    const float4 wv = ((const float4*)w)[threadIdx.x];
    const float4 bv = ((const float4*)b)[threadIdx.x];
    uint2 o;
    o.x = pack_h2((xv.x - mu) * rstd * wv.x + bv.x,
                  (xv.y - mu) * rstd * wv.y + bv.y);
    o.y = pack_h2((xv.z - mu) * rstd * wv.z + bv.z,
                  (xv.w - mu) * rstd * wv.w + bv.w);
    ((uint2*)(y + (row << 10)))[threadIdx.x] = o;
}

// ---------------------------------------------------------------------------
// Flash attention, fp16 mma.sync m16n8k16.
//   Q-tile 128 (256 threads, 8 warps). K via LDSM.x2, P via LDSM.x4,
//   V via LDSM.x2.trans. fp32 accumulators + softmax.
//   Row strides: Q/K/V 144B, P 80B -- ALL multiples of 16B (ldmatrix req).
// ---------------------------------------------------------------------------
#define QROWS   128
#define AQ_B    144
#define AK_B    144
#define AV_B    144
#define AP_B    80
#define OFF_Q   0
#define OFF_K   (QROWS * AQ_B)                         // 18432
#define OFF_V   (OFF_K + 2 * 32 * AK_B)                // 27648
#define OFF_P   (OFF_V + 2 * 32 * AV_B)                // 36864
#define ATTN_SMEM (OFF_P + QROWS * AP_B)               // 47104 B

__global__ __launch_bounds__(256, 2)
void attn_mma(const __half* __restrict__ qkv, __half* __restrict__ out)
{
    extern __shared__ char asmc[];
    const uint32_t smb = smem_u32(asmc);
    const uint32_t sQ = smb + OFF_Q, sK = smb + OFF_K;
    const uint32_t sV = smb + OFF_V, sP = smb + OFF_P;

    const int tid  = threadIdx.x;
    const int warp = tid >> 5, lane = tid & 31;
    const int qr   = lane >> 2, qc = lane & 3;
    const int lx   = lane & 7;
    const int b    = blockIdx.y >> 4, h = blockIdx.y & 15;
    const int q0   = blockIdx.x * QROWS;
    const int wm   = warp * 16;               // 0..112
    const long base = (long)b * SS * 3072 + h * 64;

    // Q tile (128 rows x 8 chunks = 1024): 4 per thread
    #pragma unroll
    for (int i = 0; i < 4; i++) {
        const int cc = tid + i * 256;
        const int row = cc >> 3, c = cc & 7;
        cp_async16(sQ + row * AQ_B + c * 16,
                   qkv + base + (long)(q0 + row) * 3072 + c * 8);
    }
    // K/V tile kt=0 (32 rows x 8 chunks = 256 each): 1 per thread each
    {
        const int row = tid >> 3, c = tid & 7;
        const long ko = base + 1024 + (long)row * 3072 + c * 8;
        cp_async16(sK + row * AK_B + c * 16, qkv + ko);
        cp_async16(sV + row * AV_B + c * 16, qkv + ko + 1024);
    }
    CP_COMMIT();
    CP_WAIT(0);
    __syncthreads();

    // Q fragments: scale by 0.125 (exact in fp16), register-resident.
    uint32_t qa[4][4];
    {
        const int r0off = OFF_Q + (wm + qr) * AQ_B + qc * 4;
        const int r1off = r0off + 8 * AQ_B;
        const __half2 s8 = __floats2half2_rn(0.125f, 0.125f);
        #pragma unroll
        for (int ks = 0; ks < 4; ks++) {
            __half2 a0 = __hmul2(*(const __half2*)(asmc + r0off + ks * 32), s8);
            __half2 a1 = __hmul2(*(const __half2*)(asmc + r1off + ks * 32), s8);
            __half2 a2 = __hmul2(*(const __half2*)(asmc + r0off + ks * 32 + 16), s8);
            __half2 a3 = __hmul2(*(const __half2*)(asmc + r1off + ks * 32 + 16), s8);
            qa[ks][0] = *(uint32_t*)&a0;
            qa[ks][1] = *(uint32_t*)&a1;
            qa[ks][2] = *(uint32_t*)&a2;
            qa[ks][3] = *(uint32_t*)&a3;
        }
    }

    const uint32_t kBit = (uint32_t)((lane >> 3) & 1);

    float o[8][4];
    #pragma unroll
    for (int nt = 0; nt < 8; nt++)
        #pragma unroll
        for (int k = 0; k < 4; k++) o[nt][k] = 0.f;
    float mrow0 = -1e30f, mrow1 = -1e30f, l0 = 0.f, l1 = 0.f;

    for (int kt = 0; kt < 32; kt++) {
        const int cur = kt & 1;
        CP_WAIT(0);
        __syncthreads();
        if (kt + 1 < 32) {
            const int nxt = cur ^ 1;
            const int row = tid >> 3, c = tid & 7;
            const long ko = base + 1024
                          + (long)((kt + 1) * 32 + row) * 3072 + c * 8;
            cp_async16(sK + (nxt * 32 + row) * AK_B + c * 16, qkv + ko);
            cp_async16(sV + (nxt * 32 + row) * AV_B + c * 16, qkv + ko + 1024);
        }
        CP_COMMIT();

        const uint32_t sKc = sK + cur * 32 * AK_B;
        const uint32_t sVc = sV + cur * 32 * AV_B;

        // S = (Q/8) K^T : 4 k16-steps, K frags LDSM.x2 (rows=keys, B-pattern)
        float s[4][4];
        #pragma unroll
        for (int nt = 0; nt < 4; nt++)
            #pragma unroll
            for (int k = 0; k < 4; k++) s[nt][k] = 0.f;
        #pragma unroll
        for (int ks = 0; ks < 4; ks++) {
            const uint32_t kAddr = sKc + (uint32_t)lx * AK_B
                                 + (((uint32_t)(ks << 1) + kBit) << 4);
            uint32_t bf[4][2];
            #pragma unroll
            for (int nt = 0; nt < 4; nt++)
                LDSM_X2(bf[nt], kAddr + nt * (8 * AK_B));
            #pragma unroll
            for (int nt = 0; nt < 4; nt++)
                MMA_F16(s[nt], qa[ks], bf[nt]);
        }

        // online softmax
        float m0 = -1e30f, m1 = -1e30f;
        #pragma unroll
        for (int nt = 0; nt < 4; nt++) {
            m0 = fmaxf(m0, fmaxf(s[nt][0], s[nt][1]));
            m1 = fmaxf(m1, fmaxf(s[nt][2], s[nt][3]));
        }
        m0 = fmaxf(m0, __shfl_xor_sync(0xffffffffu, m0, 1));
        m0 = fmaxf(m0, __shfl_xor_sync(0xffffffffu, m0, 2));
        m1 = fmaxf(m1, __shfl_xor_sync(0xffffffffu, m1, 1));
        m1 = fmaxf(m1, __shfl_xor_sync(0xffffffffu, m1, 2));
        const float n0 = fmaxf(mrow0, m0), n1 = fmaxf(mrow1, m1);
        const float c0 = __expf(mrow0 - n0), c1 = __expf(mrow1 - n1);
        float ps0 = 0.f, ps1 = 0.f;
        char* P0 = asmc + (OFF_P + (wm + qr) * AP_B + qc * 4);
        char* P1 = P0 + 8 * AP_B;
        #pragma unroll
        for (int nt = 0; nt < 4; nt++) {
            const float p00 = __expf(s[nt][0] - n0);
            const float p01 = __expf(s[nt][1] - n0);
            const float p10 = __expf(s[nt][2] - n1);
            const float p11 = __expf(s[nt][3] - n1);
            ps0 += p00 + p01;
            ps1 += p10 + p11;
            *(uint32_t*)(P0 + nt * 16) = pack_h2(p00, p01);
            *(uint32_t*)(P1 + nt * 16) = pack_h2(p10, p11);
        }
        ps0 += __shfl_xor_sync(0xffffffffu, ps0, 1);
        ps0 += __shfl_xor_sync(0xffffffffu, ps0, 2);
        ps1 += __shfl_xor_sync(0xffffffffu, ps1, 1);
        ps1 += __shfl_xor_sync(0xffffffffu, ps1, 2);
        l0 = l0 * c0 + ps0;
        l1 = l1 * c1 + ps1;
        mrow0 = n0; mrow1 = n1;
        #pragma unroll
        for (int nt = 0; nt < 8; nt++) {
            o[nt][0] *= c0; o[nt][1] *= c0;
            o[nt][2] *= c1; o[nt][3] *= c1;
        }
        __syncwarp();                          // P visible within warp

        // O += P V : 2 k16-steps (32 keys); P LDSM.x4, V LDSM.x2.trans
        #pragma unroll
        for (int ks2 = 0; ks2 < 2; ks2++) {
            uint32_t pa[4];
            const uint32_t pAddr = sP + (uint32_t)(wm + (lane & 15)) * AP_B
                                 + (((uint32_t)(ks2 << 1) + (uint32_t)(lane >> 4)) << 4);
            LDSM_X4(pa, pAddr);
            const uint32_t vRow = sVc
                + (uint32_t)(ks2 * 16 + (lane & 7) + ((lane >> 3) & 1) * 8) * AV_B;
            #pragma unroll
            for (int nt = 0; nt < 8; nt++) {
                uint32_t bv[2];
                LDSM_X2T(bv, vRow + (nt << 4));
                MMA_F16(o[nt], pa, bv);
            }
        }
        __syncwarp();                          // P reads done before next write
    }

    const float i0 = 1.0f / l0, i1 = 1.0f / l1;
    const long r0g = (long)(b * SS + q0 + wm + qr);
    __half* d0 = out + r0g * EE + h * 64 + 2 * qc;
    __half* d1 = d0 + 8 * EE;
    #pragma unroll
    for (int nt = 0; nt < 8; nt++) {
        *(uint32_t*)(d0 + nt * 8) = pack_h2(o[nt][0] * i0, o[nt][1] * i0);
        *(uint32_t*)(d1 + nt * 8) = pack_h2(o[nt][2] * i1, o[nt][3] * i1);
    }
}

// ---------------------------------------------------------------------------
// Launch sequence
// ---------------------------------------------------------------------------
extern "C" void kernel_launch(void* const* d_in, const int* in_sizes, int n_in,
                              void* d_out, int out_size)
{
    const float* x         = (const float*)d_in[0];
    const float* ln1_w     = (const float*)d_in[1];
    const float* ln1_b     = (const float*)d_in[2];
    const float* ln2_w     = (const float*)d_in[3];
    const float* ln2_b     = (const float*)d_in[4];
    const float* in_proj_w = (const float*)d_in[5];
    const float* in_proj_b = (const float*)d_in[6];
    const float* out_w     = (const float*)d_in[7];
    const float* out_b     = (const float*)d_in[8];
    const float* w1        = (const float*)d_in[9];
    const float* b1        = (const float*)d_in[10];
    const float* w2        = (const float*)d_in[11];
    const float* b2        = (const float*)d_in[12];
    float* outp            = (float*)d_out;

    __half *h, *qkv, *attn, *ffn, *wq, *wo, *w1t, *w2t;
    float  *x2;
    cudaGetSymbolAddress((void**)&h,    g_h);
    cudaGetSymbolAddress((void**)&qkv,  g_qkv);
    cudaGetSymbolAddress((void**)&attn, g_attn);
    cudaGetSymbolAddress((void**)&x2,   g_x2);
    cudaGetSymbolAddress((void**)&ffn,  g_ffn);
    cudaGetSymbolAddress((void**)&wq,   g_wq);
    cudaGetSymbolAddress((void**)&wo,   g_wo);
    cudaGetSymbolAddress((void**)&w1t,  g_w1);
    cudaGetSymbolAddress((void**)&w2t,  g_w2);

    cudaFuncSetAttribute(gemm_mma<EPI_NONE, true>,  cudaFuncAttributeMaxDynamicSharedMemorySize, DSMEM_SZ);
    cudaFuncSetAttribute(gemm_mma<EPI_GELU, true>,  cudaFuncAttributeMaxDynamicSharedMemorySize, DSMEM_SZ);
    cudaFuncSetAttribute(gemm_mma<EPI_RES,  false>, cudaFuncAttributeMaxDynamicSharedMemorySize, DSMEM_SZ);
    cudaFuncSetAttribute(attn_mma, cudaFuncAttributeMaxDynamicSharedMemorySize, ATTN_SMEM);

    // 0. pre-cast weights to fp16 (HBM-bound, ~25us total)
    half_cast<<<(3 * EE * EE / 4 + 255) / 256, 256>>>(in_proj_w, wq, 3 * EE * EE / 4);
    half_cast<<<(EE * EE / 4 + 255) / 256, 256>>>(out_w, wo, EE * EE / 4);
    half_cast<<<(FFN * EE / 4 + 255) / 256, 256>>>(w1, w1t, FFN * EE / 4);
    half_cast<<<(EE * FFN / 4 + 255) / 256, 256>>>(w2, w2t, EE * FFN / 4);

    // 1. h = fp16(LN1(x))
    ln_kernel<<<MM, 256>>>(x, ln1_w, ln1_b, h);
    // 2. qkv = fp16(h @ wq^T + b)                     [16384, 3072]
    gemm_mma<EPI_NONE, true><<<dim3(3 * EE / 128, MM / 128), 256, DSMEM_SZ>>>(
        h, wq, in_proj_b, nullptr, qkv, 3 * EE, EE);
    // 3. attention (fp16 in/out, fp32 softmax+acc)
    attn_mma<<<dim3(SS / QROWS, BB * HH), 256, ATTN_SMEM>>>(qkv, attn);
    // 4. x2 = x + attn @ wo^T + out_b                 (fp32 out)
    gemm_mma<EPI_RES, false><<<dim3(EE / 128, MM / 128), 256, DSMEM_SZ>>>(
        attn, wo, out_b, x, x2, EE, EE);
    // 5. h = fp16(LN2(x2))
    ln_kernel<<<MM, 256>>>(x2, ln2_w, ln2_b, h);
    // 6. ffn = fp16(gelu(h @ w1^T + b1))              [16384, 4096]
    gemm_mma<EPI_GELU, true><<<dim3(FFN / 128, MM / 128), 256, DSMEM_SZ>>>(
        h, w1t, b1, nullptr, ffn, FFN, EE);
    // 7. out = x2 + ffn @ w2^T + b2                   (fp32 out)
    gemm_mma<EPI_RES, false><<<dim3(EE / 128, MM / 128), 256, DSMEM_SZ>>>(
        ffn, w2t, b2, x2, outp, EE, FFN);
}